// round 13
// baseline (speedup 1.0000x reference)
#include <cuda_runtime.h>
#include <cuda_bf16.h>
#include <cuda_fp16.h>
#include <math.h>
#include <stdint.h>

#define B_    2
#define S_    2048
#define HID_  768
#define NH_   12
#define HD_   64
#define M_    (B_ * S_)          // 4096 rows
#define WHALF 64                 // WINDOW/2

// ---------------- device scratch (no allocations allowed) ------------------
// fp16 operands for projection GEMMs (2-term scheme: A hi only, W hi+lo)
__device__ __align__(16) __half gAh[M_ * HID_];
__device__ __align__(16) __half gW1h[HID_ * HID_];
__device__ __align__(16) __half gW1l[HID_ * HID_];
__device__ __align__(16) __half gW2h[HID_ * HID_];
__device__ __align__(16) __half gW2l[HID_ * HID_];

// bf16 splits for attention (3-term, written by gemm<0> epilogue)
__device__ __align__(16) __nv_bfloat16 gKh[M_ * HID_];  // q_rot hi (= k)
__device__ __align__(16) __nv_bfloat16 gKl[M_ * HID_];  // q_rot lo
__device__ __align__(16) __nv_bfloat16 gVh[M_ * HID_];  // v hi
__device__ __align__(16) __nv_bfloat16 gVl[M_ * HID_];  // v lo

// ---------------- PTX helpers (baseline ISA only) --------------------------
__device__ __forceinline__ uint32_t smem_u32(const void* p) {
    uint32_t a;
    asm("{ .reg .u64 t; cvta.to.shared.u64 t, %1; cvt.u32.u64 %0, t; }"
        : "=r"(a) : "l"(p));
    return a;
}
__device__ __forceinline__ void ldmx4(uint32_t r[4], uint32_t addr) {
    asm volatile("ldmatrix.sync.aligned.m8n8.x4.shared.b16 {%0,%1,%2,%3}, [%4];"
                 : "=r"(r[0]), "=r"(r[1]), "=r"(r[2]), "=r"(r[3]) : "r"(addr));
}
__device__ __forceinline__ void ldmx2(uint32_t r[2], uint32_t addr) {
    asm volatile("ldmatrix.sync.aligned.m8n8.x2.shared.b16 {%0,%1}, [%2];"
                 : "=r"(r[0]), "=r"(r[1]) : "r"(addr));
}
__device__ __forceinline__ void ldmx2t(uint32_t r[2], uint32_t addr) {
    asm volatile("ldmatrix.sync.aligned.m8n8.x2.trans.shared.b16 {%0,%1}, [%2];"
                 : "=r"(r[0]), "=r"(r[1]) : "r"(addr));
}
__device__ __forceinline__ void mma_bf16(float c[4], const uint32_t a[4],
                                         const uint32_t b[2]) {
    asm volatile(
        "mma.sync.aligned.m16n8k16.row.col.f32.bf16.bf16.f32 "
        "{%0,%1,%2,%3}, {%4,%5,%6,%7}, {%8,%9}, {%0,%1,%2,%3};"
        : "+f"(c[0]), "+f"(c[1]), "+f"(c[2]), "+f"(c[3])
        : "r"(a[0]), "r"(a[1]), "r"(a[2]), "r"(a[3]), "r"(b[0]), "r"(b[1]));
}
__device__ __forceinline__ void mma_f16(float c[4], const uint32_t a[4],
                                        const uint32_t b[2]) {
    asm volatile(
        "mma.sync.aligned.m16n8k16.row.col.f32.f16.f16.f32 "
        "{%0,%1,%2,%3}, {%4,%5,%6,%7}, {%8,%9}, {%0,%1,%2,%3};"
        : "+f"(c[0]), "+f"(c[1]), "+f"(c[2]), "+f"(c[3])
        : "r"(a[0]), "r"(a[1]), "r"(a[2]), "r"(a[3]), "r"(b[0]), "r"(b[1]));
}
__device__ __forceinline__ void cp16(uint32_t dst, const void* src) {
    asm volatile("cp.async.cg.shared.global [%0], [%1], 16;"
                 :: "r"(dst), "l"(src));
}
#define CP_COMMIT() asm volatile("cp.async.commit_group;" ::: "memory")
#define CP_WAIT1()  asm volatile("cp.async.wait_group 1;" ::: "memory")

#define SWZ64(off)  ((off) ^ (((off) >> 3) & 0x30))
#define SWZ128(off) ((off) ^ (((off) >> 3) & 0x70))

__device__ __forceinline__ __nv_bfloat16 bhi(float x) { return __float2bfloat16(x); }

// ---------------------------------------------------------------------------
// fp16 split converts. DST: 0 = gAh (hi only), 1 = gW1 (hi+lo), 2 = gW2.
// ---------------------------------------------------------------------------
template<int DST>
__global__ __launch_bounds__(256)
void split_f16(const float* __restrict__ src, int n) {
    __half* __restrict__ hi = (DST == 0) ? gAh : (DST == 1) ? gW1h : gW2h;
    __half* __restrict__ lo = (DST == 2) ? gW2l : gW1l;
    int i = (blockIdx.x * 256 + threadIdx.x) * 4;
    if (i >= n) return;
    float4 v = *(const float4*)(src + i);
    __half h0 = __float2half(v.x), h1 = __float2half(v.y);
    __half h2 = __float2half(v.z), h3 = __float2half(v.w);
    *(__half2*)(hi + i)     = __half2(h0, h1);
    *(__half2*)(hi + i + 2) = __half2(h2, h3);
    if (DST != 0) {
        __half l0 = __float2half(v.x - __half2float(h0));
        __half l1 = __float2half(v.y - __half2float(h1));
        __half l2 = __float2half(v.z - __half2float(h2));
        __half l3 = __float2half(v.w - __half2float(h3));
        *(__half2*)(lo + i)     = __half2(l0, l1);
        *(__half2*)(lo + i + 2) = __half2(l2, l3);
    }
}

// ---------------------------------------------------------------------------
// Pipelined HMMA GEMM, fp16 2-term: C = Ah*Wh + Ah*Wl.
// CTA tile 64x128 (384 CTAs -> much better SM balance than 192 of 128x128).
// 128 threads = 4 warps, each warp tile 64(m)x32(n).
// K chunks of 32, 3-stage cp.async pipeline (1 barrier/chunk).
// MODE 0: epilogue = RoPE + bf16 splits -> gKh/gKl, gVh/gVl.
// MODE 1: epilogue = fp32 store to out.
// smem/stage: A 4KB + Wh 8KB + Wl 8KB = 20KB; 3 stages + 1KB pad = 62464 B.
// ---------------------------------------------------------------------------
#define A_TILE_B  4096                      // 64 rows x 64 B
#define W_TILE_B  8192                      // 128 rows x 64 B
#define STAGE_B   (A_TILE_B + 2 * W_TILE_B) // 20480
#define STAGE_PITCH 132
#define GT_SMEM (1024 + 3 * STAGE_B)        // 62464; epi overlay 33792 fits
#define NCHUNK (HID_ / 32)                  // 24

template<int MODE>
__global__ __launch_bounds__(128, 3)
void gemm_mma(float* __restrict__ out) {
    extern __shared__ __align__(1024) char sm[];
    const uint32_t smb = smem_u32(sm);

    const int n0 = blockIdx.x * 128;
    const int m0 = blockIdx.y * 64;
    const int tid = threadIdx.x;
    const int wid = tid >> 5, lane = tid & 31;
    const int wn = wid * 32;              // warp n offset (0/32/64/96)

    const __half* __restrict__ Bh = (MODE == 0) ? gW1h : gW2h;
    const __half* __restrict__ Bl = (MODE == 0) ? gW1l : gW2l;

    // loader: A tile 256 segs (2/thread), W tiles 512 segs (4/thread)
    const int arowL = tid >> 2;           // 0..31
    const int asegL = tid & 3;            // 0..3
    const size_t gAr0 = (size_t)(m0 + arowL) * HID_ + asegL * 8;
    const size_t gAr1 = (size_t)(m0 + arowL + 32) * HID_ + asegL * 8;
    const uint32_t sa0 = SWZ64((uint32_t)(arowL * 64 + asegL * 16));
    const uint32_t sa1 = SWZ64((uint32_t)((arowL + 32) * 64 + asegL * 16));
    size_t gWr[4];
    uint32_t sw[4];
    #pragma unroll
    for (int k = 0; k < 4; k++) {
        const int r = (tid >> 2) + k * 32;
        gWr[k] = (size_t)(n0 + r) * HID_ + (tid & 3) * 8;
        sw[k] = SWZ64((uint32_t)(r * 64 + (tid & 3) * 16));
    }

    #define LOAD_CHUNK(cc, st)                                                \
    {                                                                         \
        const int k0_ = (cc) * 32;                                            \
        const uint32_t s_ = smb + 1024 + (st) * STAGE_B;                      \
        cp16(s_ + sa0, gAh + gAr0 + k0_);                                     \
        cp16(s_ + sa1, gAh + gAr1 + k0_);                                     \
        _Pragma("unroll")                                                     \
        for (int k = 0; k < 4; k++) {                                         \
            cp16(s_ + A_TILE_B + sw[k],            Bh + gWr[k] + k0_);        \
            cp16(s_ + A_TILE_B + W_TILE_B + sw[k], Bl + gWr[k] + k0_);        \
        }                                                                     \
    }

    float acc[4][4][4] = {};
    const int arow = lane & 15;
    const int ahalf = (lane >> 4) << 4;
    const int brow = lane & 7;
    const int bhalf = ((lane >> 3) & 1) << 4;

    LOAD_CHUNK(0, 0); CP_COMMIT();
    LOAD_CHUNK(1, 1); CP_COMMIT();

    int st = 0;
    for (int c = 0; c < NCHUNK; c++) {
        const uint32_t uA  = smb + 1024 + st * STAGE_B;
        const uint32_t uWh = uA + A_TILE_B;
        const uint32_t uWl = uA + A_TILE_B + W_TILE_B;

        CP_WAIT1();
        __syncthreads();

        if (c + 2 < NCHUNK) {
            const int st2 = (st + 2) % 3;
            LOAD_CHUNK(c + 2, st2);
        }
        CP_COMMIT();

        #pragma unroll
        for (int ks = 0; ks < 2; ks++) {
            const int kb = ks * 32;
            uint32_t ah[4][4], bh2[4][2], bl2[4][2];
            #pragma unroll
            for (int mt = 0; mt < 4; mt++) {
                const int r = mt * 16 + arow;
                ldmx4(ah[mt], uA + SWZ64(r * 64 + kb + ahalf));
            }
            #pragma unroll
            for (int nt = 0; nt < 4; nt++) {
                const int r = wn + nt * 8 + brow;
                const uint32_t off = SWZ64(r * 64 + kb + bhalf);
                ldmx2(bh2[nt], uWh + off);
                ldmx2(bl2[nt], uWl + off);
            }
            #pragma unroll
            for (int mt = 0; mt < 4; mt++)
                #pragma unroll
                for (int nt = 0; nt < 4; nt++)
                    mma_f16(acc[mt][nt], ah[mt], bh2[nt]);
            #pragma unroll
            for (int mt = 0; mt < 4; mt++)
                #pragma unroll
                for (int nt = 0; nt < 4; nt++)
                    mma_f16(acc[mt][nt], ah[mt], bl2[nt]);
        }
        st = (st + 1) % 3;
    }
    #undef LOAD_CHUNK
    __syncthreads();

    // ---- epilogue: stage in smem [64][132], then coalesced processing ----
    float* stage = (float*)sm;
    #pragma unroll
    for (int mt = 0; mt < 4; mt++)
        #pragma unroll
        for (int nt = 0; nt < 4; nt++) {
            const int r = mt * 16 + (lane >> 2);
            const int cc = wn + nt * 8 + 2 * (lane & 3);
            *(float2*)&stage[r * STAGE_PITCH + cc] =
                make_float2(acc[mt][nt][0], acc[mt][nt][1]);
            *(float2*)&stage[(r + 8) * STAGE_PITCH + cc] =
                make_float2(acc[mt][nt][2], acc[mt][nt][3]);
        }
    __syncthreads();

    const int row = tid >> 1;            // 0..63
    const int hh  = tid & 1;             // 64-col head half
    const int m = m0 + row;
    const float* srow = &stage[row * STAGE_PITCH + hh * 64];
    if (MODE == 0) {
        const float pos = (float)(m & (S_ - 1));
        float vb[64], rb[64];
        #pragma unroll
        for (int d = 0; d < 32; d++) {
            const float qlo = srow[d];
            const float qhi = srow[d + 32];
            const float inv = exp2f((float)d * -0.41524101186920654f);
            float sn, cs;
            sincosf(pos * inv, &sn, &cs);
            vb[d] = qlo;      vb[d + 32] = qhi;
            rb[d] = qlo * cs - qhi * sn;
            rb[d + 32] = qhi * cs + qlo * sn;
        }
        const size_t base = (size_t)m * HID_ + n0 + hh * 64;
        #pragma unroll
        for (int q = 0; q < 8; q++) {
            __nv_bfloat162 kh4[4], kl4[4], vh4[4], vl4[4];
            #pragma unroll
            for (int e = 0; e < 4; e++) {
                float v0 = vb[q * 8 + 2 * e], v1 = vb[q * 8 + 2 * e + 1];
                float r0 = rb[q * 8 + 2 * e], r1 = rb[q * 8 + 2 * e + 1];
                __nv_bfloat16 vh0 = bhi(v0), vh1 = bhi(v1);
                __nv_bfloat16 rh0 = bhi(r0), rh1 = bhi(r1);
                vh4[e] = __nv_bfloat162(vh0, vh1);
                vl4[e] = __nv_bfloat162(bhi(v0 - __bfloat162float(vh0)),
                                        bhi(v1 - __bfloat162float(vh1)));
                kh4[e] = __nv_bfloat162(rh0, rh1);
                kl4[e] = __nv_bfloat162(bhi(r0 - __bfloat162float(rh0)),
                                        bhi(r1 - __bfloat162float(rh1)));
            }
            *(int4*)(gKh + base + q * 8) = *(int4*)kh4;
            *(int4*)(gKl + base + q * 8) = *(int4*)kl4;
            *(int4*)(gVh + base + q * 8) = *(int4*)vh4;
            *(int4*)(gVl + base + q * 8) = *(int4*)vl4;
        }
    } else {
        float* op = &out[(size_t)m * HID_ + n0 + hh * 64];
        #pragma unroll
        for (int q = 0; q < 16; q++) {
            float4 f = make_float4(srow[q * 4], srow[q * 4 + 1],
                                   srow[q * 4 + 2], srow[q * 4 + 3]);
            *(float4*)(op + q * 4) = f;
        }
    }
}

// ---------------------------------------------------------------------------
// HMMA sliding-window attention (3-term bf16, unchanged). Epilogue writes
// fp16 hi only -> gAh (gemm<1> is 2-term on the A side).
// ---------------------------------------------------------------------------
#define QH_OFF  0
#define QL_OFF  8192
#define KVH_OFF 16384
#define KVL_OFF 24576
#define PH_OFF  32768
#define PL_OFF  58368
#define RED_OFF 83968
#define AT_SMEM 84992
#define P_PITCH 400

__global__ __launch_bounds__(256, 2)
void attn_mma() {
    extern __shared__ __align__(1024) char sm[];
    const uint32_t smb = smem_u32(sm);

    const int t0 = blockIdx.x * 64;
    const int bh = blockIdx.y;
    const int b = bh / NH_, h = bh % NH_;
    const int tid = threadIdx.x;
    const int wid = tid >> 5, lane = tid & 31;
    const int wm2 = (wid >> 2) * 32;
    const int wg  = wid & 3;
    const int wn2 = wg * 16;

    const int arow = lane & 15;
    const int ahalf = (lane >> 4) << 4;
    const int brow = lane & 7;
    const int bhalf = ((lane >> 3) & 1) << 4;

    float* red = (float*)(sm + RED_OFF);

    #pragma unroll
    for (int t = 0; t < 2; t++) {
        const int seg = tid + t * 256;
        const int row = seg >> 3, sc = seg & 7;
        const size_t g = ((size_t)(b * S_ + t0 + row)) * HID_ + h * 64 + sc * 8;
        const uint32_t off = SWZ128((uint32_t)(row * 128 + sc * 16));
        *(int4*)(sm + QH_OFF + off) = *(const int4*)(gKh + g);
        *(int4*)(sm + QL_OFF + off) = *(const int4*)(gKl + g);
    }

    float sacc[3][2][2][4] = {};
    for (int kc = 0; kc < 3; kc++) {
        const int s0 = t0 - 64 + kc * 64;
        __syncthreads();
        #pragma unroll
        for (int t = 0; t < 2; t++) {
            const int seg = tid + t * 256;
            const int row = seg >> 3, sc = seg & 7;
            const int s = s0 + row;
            int4 vh = make_int4(0, 0, 0, 0), vl = make_int4(0, 0, 0, 0);
            if ((unsigned)s < (unsigned)S_) {
                const size_t g = ((size_t)(b * S_ + s)) * HID_ + h * 64 + sc * 8;
                vh = *(const int4*)(gKh + g);
                vl = *(const int4*)(gKl + g);
            }
            const uint32_t off = SWZ128((uint32_t)(row * 128 + sc * 16));
            *(int4*)(sm + KVH_OFF + off) = vh;
            *(int4*)(sm + KVL_OFF + off) = vl;
        }
        __syncthreads();

        #pragma unroll
        for (int ks = 0; ks < 4; ks++) {
            const int kb = ks * 32;
            uint32_t qh_[2][4], ql_[2][4], kh_[2][2], kl_[2][2];
            #pragma unroll
            for (int mt = 0; mt < 2; mt++) {
                const uint32_t ao = SWZ128((wm2 + mt * 16 + arow) * 128 + kb + ahalf);
                ldmx4(qh_[mt], smb + QH_OFF + ao);
                ldmx4(ql_[mt], smb + QL_OFF + ao);
            }
            #pragma unroll
            for (int nt = 0; nt < 2; nt++) {
                const uint32_t bo = SWZ128((wn2 + nt * 8 + brow) * 128 + kb + bhalf);
                ldmx2(kh_[nt], smb + KVH_OFF + bo);
                ldmx2(kl_[nt], smb + KVL_OFF + bo);
            }
            #pragma unroll
            for (int mt = 0; mt < 2; mt++)
                #pragma unroll
                for (int nt = 0; nt < 2; nt++) {
                    mma_bf16(sacc[kc][mt][nt], qh_[mt], kh_[nt]);
                    mma_bf16(sacc[kc][mt][nt], qh_[mt], kl_[nt]);
                    mma_bf16(sacc[kc][mt][nt], ql_[mt], kh_[nt]);
                }
        }
    }

    #pragma unroll
    for (int kc = 0; kc < 3; kc++)
        #pragma unroll
        for (int mt = 0; mt < 2; mt++)
            #pragma unroll
            for (int nt = 0; nt < 2; nt++)
                #pragma unroll
                for (int j = 0; j < 4; j++) {
                    const int row = wm2 + mt * 16 + (lane >> 2) + (j >> 1) * 8;
                    const int col = kc * 64 + wn2 + nt * 8 + 2 * (lane & 3) + (j & 1);
                    const int t = t0 + row;
                    const int s = t0 - 64 + col;
                    int dist = t - s; if (dist < 0) dist = -dist;
                    const bool valid = ((unsigned)s < (unsigned)S_) && (dist <= WHALF);
                    sacc[kc][mt][nt][j] = valid ? sacc[kc][mt][nt][j] * 0.125f : -1e30f;
                }

    float rmax[2][2];
    #pragma unroll
    for (int mt = 0; mt < 2; mt++)
        #pragma unroll
        for (int hf = 0; hf < 2; hf++) {
            float m = -1e30f;
            #pragma unroll
            for (int kc = 0; kc < 3; kc++)
                #pragma unroll
                for (int nt = 0; nt < 2; nt++) {
                    m = fmaxf(m, sacc[kc][mt][nt][hf * 2]);
                    m = fmaxf(m, sacc[kc][mt][nt][hf * 2 + 1]);
                }
            m = fmaxf(m, __shfl_xor_sync(0xffffffffu, m, 1));
            m = fmaxf(m, __shfl_xor_sync(0xffffffffu, m, 2));
            rmax[mt][hf] = m;
        }
    #pragma unroll
    for (int mt = 0; mt < 2; mt++)
        #pragma unroll
        for (int hf = 0; hf < 2; hf++)
            red[(wm2 + mt * 16 + (lane >> 2) + hf * 8) * 4 + wg] = rmax[mt][hf];
    __syncthreads();
    #pragma unroll
    for (int mt = 0; mt < 2; mt++)
        #pragma unroll
        for (int hf = 0; hf < 2; hf++) {
            const int r = wm2 + mt * 16 + (lane >> 2) + hf * 8;
            rmax[mt][hf] = fmaxf(fmaxf(red[r * 4], red[r * 4 + 1]),
                                 fmaxf(red[r * 4 + 2], red[r * 4 + 3]));
        }
    __syncthreads();

    float rsum[2][2];
    #pragma unroll
    for (int mt = 0; mt < 2; mt++)
        #pragma unroll
        for (int hf = 0; hf < 2; hf++) {
            float s = 0.0f;
            #pragma unroll
            for (int kc = 0; kc < 3; kc++)
                #pragma unroll
                for (int nt = 0; nt < 2; nt++)
                    #pragma unroll
                    for (int e = 0; e < 2; e++) {
                        float p = __expf(sacc[kc][mt][nt][hf * 2 + e] - rmax[mt][hf]);
                        sacc[kc][mt][nt][hf * 2 + e] = p;
                        s += p;
                    }
            s += __shfl_xor_sync(0xffffffffu, s, 1);
            s += __shfl_xor_sync(0xffffffffu, s, 2);
            rsum[mt][hf] = s;
        }
    #pragma unroll
    for (int mt = 0; mt < 2; mt++)
        #pragma unroll
        for (int hf = 0; hf < 2; hf++)
            red[(wm2 + mt * 16 + (lane >> 2) + hf * 8) * 4 + wg] = rsum[mt][hf];
    __syncthreads();
    #pragma unroll
    for (int mt = 0; mt < 2; mt++)
        #pragma unroll
        for (int hf = 0; hf < 2; hf++) {
            const int r = wm2 + mt * 16 + (lane >> 2) + hf * 8;
            rsum[mt][hf] = 1.0f / (red[r * 4] + red[r * 4 + 1] +
                                   red[r * 4 + 2] + red[r * 4 + 3]);
        }

    #pragma unroll
    for (int kc = 0; kc < 3; kc++)
        #pragma unroll
        for (int mt = 0; mt < 2; mt++)
            #pragma unroll
            for (int nt = 0; nt < 2; nt++)
                #pragma unroll
                for (int hf = 0; hf < 2; hf++) {
                    const int row = wm2 + mt * 16 + (lane >> 2) + hf * 8;
                    const int col = kc * 64 + wn2 + nt * 8 + 2 * (lane & 3);
                    float p0 = sacc[kc][mt][nt][hf * 2]     * rsum[mt][hf];
                    float p1 = sacc[kc][mt][nt][hf * 2 + 1] * rsum[mt][hf];
                    __nv_bfloat16 h0 = bhi(p0), h1 = bhi(p1);
                    __nv_bfloat162 ph2(h0, h1);
                    __nv_bfloat162 pl2(bhi(p0 - __bfloat162float(h0)),
                                       bhi(p1 - __bfloat162float(h1)));
                    *(__nv_bfloat162*)(sm + PH_OFF + row * P_PITCH + col * 2) = ph2;
                    *(__nv_bfloat162*)(sm + PL_OFF + row * P_PITCH + col * 2) = pl2;
                }

    const int wn2v = wg * 16;
    float oacc[2][2][4] = {};
    for (int kc = 0; kc < 3; kc++) {
        const int s0 = t0 - 64 + kc * 64;
        __syncthreads();
        #pragma unroll
        for (int t = 0; t < 2; t++) {
            const int seg = tid + t * 256;
            const int row = seg >> 3, sc = seg & 7;
            const int s = s0 + row;
            int4 vh = make_int4(0, 0, 0, 0), vl = make_int4(0, 0, 0, 0);
            if ((unsigned)s < (unsigned)S_) {
                const size_t g = ((size_t)(b * S_ + s)) * HID_ + h * 64 + sc * 8;
                vh = *(const int4*)(gVh + g);
                vl = *(const int4*)(gVl + g);
            }
            const uint32_t off = SWZ128((uint32_t)(row * 128 + sc * 16));
            *(int4*)(sm + KVH_OFF + off) = vh;
            *(int4*)(sm + KVL_OFF + off) = vl;
        }
        __syncthreads();

        #pragma unroll
        for (int ks = 0; ks < 4; ks++) {
            uint32_t pa_h[2][4], pa_l[2][4], vh_[2][2], vl_[2][2];
            #pragma unroll
            for (int mt = 0; mt < 2; mt++) {
                const uint32_t ao = (uint32_t)((wm2 + mt * 16 + arow) * P_PITCH
                                               + kc * 128 + ks * 32 + ahalf);
                ldmx4(pa_h[mt], smb + PH_OFF + ao);
                ldmx4(pa_l[mt], smb + PL_OFF + ao);
            }
            const int krow = ks * 16 + arow;
            #pragma unroll
            for (int nt = 0; nt < 2; nt++) {
                const uint32_t bo = SWZ128((uint32_t)(krow * 128
                                           + (wn2v + nt * 8) * 2));
                ldmx2t(vh_[nt], smb + KVH_OFF + bo);
                ldmx2t(vl_[nt], smb + KVL_OFF + bo);
            }
            #pragma unroll
            for (int mt = 0; mt < 2; mt++)
                #pragma unroll
                for (int nt = 0; nt < 2; nt++) {
                    mma_bf16(oacc[mt][nt], pa_h[mt], vh_[nt]);
                    mma_bf16(oacc[mt][nt], pa_h[mt], vl_[nt]);
                    mma_bf16(oacc[mt][nt], pa_l[mt], vh_[nt]);
                }
        }
    }

    // ---- epilogue: stage O, then convert to fp16 gAh (hi only) ----
    __syncthreads();
    float* stage = (float*)(sm + PH_OFF);   // [64][68]
    #pragma unroll
    for (int mt = 0; mt < 2; mt++)
        #pragma unroll
        for (int nt = 0; nt < 2; nt++) {
            const int r = wm2 + mt * 16 + (lane >> 2);
            const int c = wn2v + nt * 8 + 2 * (lane & 3);
            *(float2*)&stage[r * 68 + c] = make_float2(oacc[mt][nt][0], oacc[mt][nt][1]);
            *(float2*)&stage[(r + 8) * 68 + c] = make_float2(oacc[mt][nt][2], oacc[mt][nt][3]);
        }
    __syncthreads();
    {
        const int row = tid >> 2, q4 = tid & 3;
        const size_t base = ((size_t)(b * S_ + t0 + row)) * HID_ + h * 64 + q4 * 16;
        const float* sp = &stage[row * 68 + q4 * 16];
        __half2 hbuf[8];
        #pragma unroll
        for (int e = 0; e < 8; e++)
            hbuf[e] = __floats2half2_rn(sp[2 * e], sp[2 * e + 1]);
        *(int4*)(gAh + base)     = *(int4*)&hbuf[0];
        *(int4*)(gAh + base + 8) = *(int4*)&hbuf[4];
    }
}

// ---------------------------------------------------------------------------
extern "C" void kernel_launch(void* const* d_in, const int* in_sizes, int n_in,
                              void* d_out, int out_size) {
    const float* hidden = (const float*)d_in[0];
    const float* Wq     = (const float*)d_in[1];
    const float* Wo     = (const float*)d_in[2];
    float* out = (float*)d_out;
    (void)in_sizes; (void)n_in; (void)out_size;

    cudaFuncSetAttribute(gemm_mma<0>,
                         cudaFuncAttributeMaxDynamicSharedMemorySize, GT_SMEM);
    cudaFuncSetAttribute(gemm_mma<1>,
                         cudaFuncAttributeMaxDynamicSharedMemorySize, GT_SMEM);
    cudaFuncSetAttribute(attn_mma,
                         cudaFuncAttributeMaxDynamicSharedMemorySize, AT_SMEM);

    split_f16<0><<<(M_ * HID_ / 4 + 255) / 256, 256>>>(hidden, M_ * HID_);
    split_f16<1><<<(HID_ * HID_ / 4 + 255) / 256, 256>>>(Wq, HID_ * HID_);
    split_f16<2><<<(HID_ * HID_ / 4 + 255) / 256, 256>>>(Wo, HID_ * HID_);

    dim3 gemm_grid(HID_ / 128, M_ / 64);    // (6, 64) = 384 CTAs
    gemm_mma<0><<<gemm_grid, 128, GT_SMEM>>>(nullptr);

    dim3 attn_grid(S_ / 64, B_ * NH_);
    attn_mma<<<attn_grid, 256, AT_SMEM>>>();   // writes fp16 gAh for gemm<1>

    gemm_mma<1><<<gemm_grid, 128, GT_SMEM>>>(out);
}

// round 14
// speedup vs baseline: 1.4209x; 1.4209x over previous
#include <cuda_runtime.h>
#include <cuda_bf16.h>
#include <cuda_fp16.h>
#include <math.h>
#include <stdint.h>

#define B_    2
#define S_    2048
#define HID_  768
#define NH_   12
#define HD_   64
#define M_    (B_ * S_)          // 4096 rows
#define WHALF 64                 // WINDOW/2

// ---------------- device scratch (no allocations allowed) ------------------
// fp16 operands for projection GEMMs (2-term scheme: A hi only, W hi+lo)
__device__ __align__(16) __half gAh[M_ * HID_];
__device__ __align__(16) __half gW1h[HID_ * HID_];
__device__ __align__(16) __half gW1l[HID_ * HID_];
__device__ __align__(16) __half gW2h[HID_ * HID_];
__device__ __align__(16) __half gW2l[HID_ * HID_];

// bf16 splits for attention (3-term, written by gemm<0> epilogue)
__device__ __align__(16) __nv_bfloat16 gKh[M_ * HID_];  // q_rot hi (= k)
__device__ __align__(16) __nv_bfloat16 gKl[M_ * HID_];  // q_rot lo
__device__ __align__(16) __nv_bfloat16 gVh[M_ * HID_];  // v hi
__device__ __align__(16) __nv_bfloat16 gVl[M_ * HID_];  // v lo

// ---------------- PTX helpers (baseline ISA only) --------------------------
__device__ __forceinline__ uint32_t smem_u32(const void* p) {
    uint32_t a;
    asm("{ .reg .u64 t; cvta.to.shared.u64 t, %1; cvt.u32.u64 %0, t; }"
        : "=r"(a) : "l"(p));
    return a;
}
__device__ __forceinline__ void ldmx4(uint32_t r[4], uint32_t addr) {
    asm volatile("ldmatrix.sync.aligned.m8n8.x4.shared.b16 {%0,%1,%2,%3}, [%4];"
                 : "=r"(r[0]), "=r"(r[1]), "=r"(r[2]), "=r"(r[3]) : "r"(addr));
}
__device__ __forceinline__ void ldmx2(uint32_t r[2], uint32_t addr) {
    asm volatile("ldmatrix.sync.aligned.m8n8.x2.shared.b16 {%0,%1}, [%2];"
                 : "=r"(r[0]), "=r"(r[1]) : "r"(addr));
}
__device__ __forceinline__ void ldmx2t(uint32_t r[2], uint32_t addr) {
    asm volatile("ldmatrix.sync.aligned.m8n8.x2.trans.shared.b16 {%0,%1}, [%2];"
                 : "=r"(r[0]), "=r"(r[1]) : "r"(addr));
}
__device__ __forceinline__ void mma_bf16(float c[4], const uint32_t a[4],
                                         const uint32_t b[2]) {
    asm volatile(
        "mma.sync.aligned.m16n8k16.row.col.f32.bf16.bf16.f32 "
        "{%0,%1,%2,%3}, {%4,%5,%6,%7}, {%8,%9}, {%0,%1,%2,%3};"
        : "+f"(c[0]), "+f"(c[1]), "+f"(c[2]), "+f"(c[3])
        : "r"(a[0]), "r"(a[1]), "r"(a[2]), "r"(a[3]), "r"(b[0]), "r"(b[1]));
}
__device__ __forceinline__ void mma_f16(float c[4], const uint32_t a[4],
                                        const uint32_t b[2]) {
    asm volatile(
        "mma.sync.aligned.m16n8k16.row.col.f32.f16.f16.f32 "
        "{%0,%1,%2,%3}, {%4,%5,%6,%7}, {%8,%9}, {%0,%1,%2,%3};"
        : "+f"(c[0]), "+f"(c[1]), "+f"(c[2]), "+f"(c[3])
        : "r"(a[0]), "r"(a[1]), "r"(a[2]), "r"(a[3]), "r"(b[0]), "r"(b[1]));
}
__device__ __forceinline__ void cp16(uint32_t dst, const void* src) {
    asm volatile("cp.async.cg.shared.global [%0], [%1], 16;"
                 :: "r"(dst), "l"(src));
}
#define CP_COMMIT() asm volatile("cp.async.commit_group;" ::: "memory")
#define CP_WAIT1()  asm volatile("cp.async.wait_group 1;" ::: "memory")

#define SWZ64(off)  ((off) ^ (((off) >> 3) & 0x30))
#define SWZ128(off) ((off) ^ (((off) >> 3) & 0x70))

__device__ __forceinline__ __nv_bfloat16 bhi(float x) { return __float2bfloat16(x); }

// ---------------------------------------------------------------------------
// fp16 split converts. DST: 0 = gAh (hi only), 1 = gW1 (hi+lo), 2 = gW2.
// ---------------------------------------------------------------------------
template<int DST>
__global__ __launch_bounds__(256)
void split_f16(const float* __restrict__ src, int n) {
    __half* __restrict__ hi = (DST == 0) ? gAh : (DST == 1) ? gW1h : gW2h;
    __half* __restrict__ lo = (DST == 2) ? gW2l : gW1l;
    int i = (blockIdx.x * 256 + threadIdx.x) * 4;
    if (i >= n) return;
    float4 v = *(const float4*)(src + i);
    __half h0 = __float2half(v.x), h1 = __float2half(v.y);
    __half h2 = __float2half(v.z), h3 = __float2half(v.w);
    *(__half2*)(hi + i)     = __half2(h0, h1);
    *(__half2*)(hi + i + 2) = __half2(h2, h3);
    if (DST != 0) {
        __half l0 = __float2half(v.x - __half2float(h0));
        __half l1 = __float2half(v.y - __half2float(h1));
        __half l2 = __float2half(v.z - __half2float(h2));
        __half l3 = __float2half(v.w - __half2float(h3));
        *(__half2*)(lo + i)     = __half2(l0, l1);
        *(__half2*)(lo + i + 2) = __half2(l2, l3);
    }
}

// ---------------------------------------------------------------------------
// Pipelined HMMA GEMM, fp16 2-term: C = Ah*Wh + Ah*Wl.
// CTA tile 64x128, 256 threads = 8 warps in 2(m)x4(n), warp tile 32x32
// (acc = 32 regs -> low pressure; 2 CTA/SM keeps 4 warps/SMSP for latency
// hiding; 384 CTAs balance far better than 192).
// K chunks of 32, 3-stage cp.async pipeline (1 barrier/chunk).
// MODE 0: epilogue = RoPE + bf16 splits -> gKh/gKl, gVh/gVl.
// MODE 1: epilogue = fp32 store to out.
// smem/stage: A 4KB + Wh 8KB + Wl 8KB = 20KB; 3 stages + 1KB = 62464 B.
// ---------------------------------------------------------------------------
#define A_TILE_B  4096                      // 64 rows x 64 B
#define W_TILE_B  8192                      // 128 rows x 64 B
#define STAGE_B   (A_TILE_B + 2 * W_TILE_B) // 20480
#define STAGE_PITCH 132
#define GT_SMEM (1024 + 3 * STAGE_B)        // 62464; epi overlay 33792 fits
#define NCHUNK (HID_ / 32)                  // 24

template<int MODE>
__global__ __launch_bounds__(256, 2)
void gemm_mma(float* __restrict__ out) {
    extern __shared__ __align__(1024) char sm[];
    const uint32_t smb = smem_u32(sm);

    const int n0 = blockIdx.x * 128;
    const int m0 = blockIdx.y * 64;
    const int tid = threadIdx.x;
    const int wid = tid >> 5, lane = tid & 31;
    const int wm = (wid >> 2) * 32;       // warp m offset (0/32)
    const int wn = (wid & 3) * 32;        // warp n offset (0/32/64/96)

    const __half* __restrict__ Bh = (MODE == 0) ? gW1h : gW2h;
    const __half* __restrict__ Bl = (MODE == 0) ? gW1l : gW2l;

    // loader (256 thr): A tile 256 segs (1/thread), W tiles 512 segs (2/thread)
    const int lrow = tid >> 2;            // 0..63
    const int lseg = tid & 3;
    const size_t gAr = (size_t)(m0 + lrow) * HID_ + lseg * 8;
    const uint32_t sa = SWZ64((uint32_t)(lrow * 64 + lseg * 16));
    const size_t gWr0 = (size_t)(n0 + lrow) * HID_ + lseg * 8;
    const size_t gWr1 = (size_t)(n0 + lrow + 64) * HID_ + lseg * 8;
    const uint32_t sw0 = SWZ64((uint32_t)(lrow * 64 + lseg * 16));
    const uint32_t sw1 = SWZ64((uint32_t)((lrow + 64) * 64 + lseg * 16));

    #define LOAD_CHUNK(cc, st)                                                \
    {                                                                         \
        const int k0_ = (cc) * 32;                                            \
        const uint32_t s_ = smb + 1024 + (st) * STAGE_B;                      \
        cp16(s_ + sa, gAh + gAr + k0_);                                       \
        cp16(s_ + A_TILE_B + sw0,            Bh + gWr0 + k0_);                \
        cp16(s_ + A_TILE_B + sw1,            Bh + gWr1 + k0_);                \
        cp16(s_ + A_TILE_B + W_TILE_B + sw0, Bl + gWr0 + k0_);                \
        cp16(s_ + A_TILE_B + W_TILE_B + sw1, Bl + gWr1 + k0_);                \
    }

    float acc[2][4][4] = {};
    const int arow = lane & 15;
    const int ahalf = (lane >> 4) << 4;
    const int brow = lane & 7;
    const int bhalf = ((lane >> 3) & 1) << 4;

    LOAD_CHUNK(0, 0); CP_COMMIT();
    LOAD_CHUNK(1, 1); CP_COMMIT();

    int st = 0;
    for (int c = 0; c < NCHUNK; c++) {
        const uint32_t uA  = smb + 1024 + st * STAGE_B;
        const uint32_t uWh = uA + A_TILE_B;
        const uint32_t uWl = uA + A_TILE_B + W_TILE_B;

        CP_WAIT1();
        __syncthreads();

        if (c + 2 < NCHUNK) {
            const int st2 = (st + 2) % 3;
            LOAD_CHUNK(c + 2, st2);
        }
        CP_COMMIT();

        #pragma unroll
        for (int ks = 0; ks < 2; ks++) {
            const int kb = ks * 32;
            uint32_t ah[2][4], bh2[4][2], bl2[4][2];
            #pragma unroll
            for (int mt = 0; mt < 2; mt++) {
                const int r = wm + mt * 16 + arow;
                ldmx4(ah[mt], uA + SWZ64(r * 64 + kb + ahalf));
            }
            #pragma unroll
            for (int nt = 0; nt < 4; nt++) {
                const int r = wn + nt * 8 + brow;
                const uint32_t off = SWZ64(r * 64 + kb + bhalf);
                ldmx2(bh2[nt], uWh + off);
                ldmx2(bl2[nt], uWl + off);
            }
            #pragma unroll
            for (int mt = 0; mt < 2; mt++)
                #pragma unroll
                for (int nt = 0; nt < 4; nt++)
                    mma_f16(acc[mt][nt], ah[mt], bh2[nt]);
            #pragma unroll
            for (int mt = 0; mt < 2; mt++)
                #pragma unroll
                for (int nt = 0; nt < 4; nt++)
                    mma_f16(acc[mt][nt], ah[mt], bl2[nt]);
        }
        st = (st + 1) % 3;
    }
    #undef LOAD_CHUNK
    __syncthreads();

    // ---- epilogue: stage C in smem [64][132] fp32 ----
    float* stage = (float*)sm;
    #pragma unroll
    for (int mt = 0; mt < 2; mt++)
        #pragma unroll
        for (int nt = 0; nt < 4; nt++) {
            const int r = wm + mt * 16 + (lane >> 2);
            const int cc = wn + nt * 8 + 2 * (lane & 3);
            *(float2*)&stage[r * STAGE_PITCH + cc] =
                make_float2(acc[mt][nt][0], acc[mt][nt][1]);
            *(float2*)&stage[(r + 8) * STAGE_PITCH + cc] =
                make_float2(acc[mt][nt][2], acc[mt][nt][3]);
        }
    __syncthreads();

    const int row = tid >> 2;            // 0..63
    const int sub = tid & 3;
    const int m = m0 + row;
    if (MODE == 0) {
        // thread owns head half hh, 16-col quarter q: cols q*16..+15 (lo, d)
        // paired with cols q*16+32..+15 (hi, d+32) of the same 64-col head.
        const int hh = sub >> 1, q = sub & 1;
        const float* srow = &stage[row * STAGE_PITCH + hh * 64 + q * 16];
        const float pos = (float)(m & (S_ - 1));
        float vb[32], rb[32];   // [0..15] lo cols, [16..31] hi cols
        #pragma unroll
        for (int j = 0; j < 16; j++) {
            const int d = q * 16 + j;
            const float qlo = srow[j];
            const float qhi = srow[j + 32];
            const float inv = exp2f((float)d * -0.41524101186920654f);
            float sn, cs;
            sincosf(pos * inv, &sn, &cs);
            vb[j] = qlo;          vb[16 + j] = qhi;
            rb[j] = qlo * cs - qhi * sn;
            rb[16 + j] = qhi * cs + qlo * sn;
        }
        const size_t base = (size_t)m * HID_ + n0 + hh * 64 + q * 16;
        #pragma unroll
        for (int half = 0; half < 2; half++) {       // lo cols, hi cols
            const size_t gb = base + half * 32;
            const float* vv = &vb[half * 16];
            const float* rr = &rb[half * 16];
            __nv_bfloat162 kh4[8], kl4[8], vh4[8], vl4[8];
            #pragma unroll
            for (int e = 0; e < 8; e++) {
                float v0 = vv[2 * e], v1 = vv[2 * e + 1];
                float r0 = rr[2 * e], r1 = rr[2 * e + 1];
                __nv_bfloat16 vh0 = bhi(v0), vh1 = bhi(v1);
                __nv_bfloat16 rh0 = bhi(r0), rh1 = bhi(r1);
                vh4[e] = __nv_bfloat162(vh0, vh1);
                vl4[e] = __nv_bfloat162(bhi(v0 - __bfloat162float(vh0)),
                                        bhi(v1 - __bfloat162float(vh1)));
                kh4[e] = __nv_bfloat162(rh0, rh1);
                kl4[e] = __nv_bfloat162(bhi(r0 - __bfloat162float(rh0)),
                                        bhi(r1 - __bfloat162float(rh1)));
            }
            *(int4*)(gKh + gb)     = *(int4*)&kh4[0];
            *(int4*)(gKh + gb + 8) = *(int4*)&kh4[4];
            *(int4*)(gKl + gb)     = *(int4*)&kl4[0];
            *(int4*)(gKl + gb + 8) = *(int4*)&kl4[4];
            *(int4*)(gVh + gb)     = *(int4*)&vh4[0];
            *(int4*)(gVh + gb + 8) = *(int4*)&vh4[4];
            *(int4*)(gVl + gb)     = *(int4*)&vl4[0];
            *(int4*)(gVl + gb + 8) = *(int4*)&vl4[4];
        }
    } else {
        const float* srow = &stage[row * STAGE_PITCH + sub * 32];
        float* op = &out[(size_t)m * HID_ + n0 + sub * 32];
        #pragma unroll
        for (int qq = 0; qq < 8; qq++) {
            float4 f = make_float4(srow[qq * 4], srow[qq * 4 + 1],
                                   srow[qq * 4 + 2], srow[qq * 4 + 3]);
            *(float4*)(op + qq * 4) = f;
        }
    }
}

// ---------------------------------------------------------------------------
// HMMA sliding-window attention (3-term bf16, unchanged). Epilogue writes
// fp16 hi only -> gAh (gemm<1> is 2-term on the A side).
// ---------------------------------------------------------------------------
#define QH_OFF  0
#define QL_OFF  8192
#define KVH_OFF 16384
#define KVL_OFF 24576
#define PH_OFF  32768
#define PL_OFF  58368
#define RED_OFF 83968
#define AT_SMEM 84992
#define P_PITCH 400

__global__ __launch_bounds__(256, 2)
void attn_mma() {
    extern __shared__ __align__(1024) char sm[];
    const uint32_t smb = smem_u32(sm);

    const int t0 = blockIdx.x * 64;
    const int bh = blockIdx.y;
    const int b = bh / NH_, h = bh % NH_;
    const int tid = threadIdx.x;
    const int wid = tid >> 5, lane = tid & 31;
    const int wm2 = (wid >> 2) * 32;
    const int wg  = wid & 3;
    const int wn2 = wg * 16;

    const int arow = lane & 15;
    const int ahalf = (lane >> 4) << 4;
    const int brow = lane & 7;
    const int bhalf = ((lane >> 3) & 1) << 4;

    float* red = (float*)(sm + RED_OFF);

    #pragma unroll
    for (int t = 0; t < 2; t++) {
        const int seg = tid + t * 256;
        const int row = seg >> 3, sc = seg & 7;
        const size_t g = ((size_t)(b * S_ + t0 + row)) * HID_ + h * 64 + sc * 8;
        const uint32_t off = SWZ128((uint32_t)(row * 128 + sc * 16));
        *(int4*)(sm + QH_OFF + off) = *(const int4*)(gKh + g);
        *(int4*)(sm + QL_OFF + off) = *(const int4*)(gKl + g);
    }

    float sacc[3][2][2][4] = {};
    for (int kc = 0; kc < 3; kc++) {
        const int s0 = t0 - 64 + kc * 64;
        __syncthreads();
        #pragma unroll
        for (int t = 0; t < 2; t++) {
            const int seg = tid + t * 256;
            const int row = seg >> 3, sc = seg & 7;
            const int s = s0 + row;
            int4 vh = make_int4(0, 0, 0, 0), vl = make_int4(0, 0, 0, 0);
            if ((unsigned)s < (unsigned)S_) {
                const size_t g = ((size_t)(b * S_ + s)) * HID_ + h * 64 + sc * 8;
                vh = *(const int4*)(gKh + g);
                vl = *(const int4*)(gKl + g);
            }
            const uint32_t off = SWZ128((uint32_t)(row * 128 + sc * 16));
            *(int4*)(sm + KVH_OFF + off) = vh;
            *(int4*)(sm + KVL_OFF + off) = vl;
        }
        __syncthreads();

        #pragma unroll
        for (int ks = 0; ks < 4; ks++) {
            const int kb = ks * 32;
            uint32_t qh_[2][4], ql_[2][4], kh_[2][2], kl_[2][2];
            #pragma unroll
            for (int mt = 0; mt < 2; mt++) {
                const uint32_t ao = SWZ128((wm2 + mt * 16 + arow) * 128 + kb + ahalf);
                ldmx4(qh_[mt], smb + QH_OFF + ao);
                ldmx4(ql_[mt], smb + QL_OFF + ao);
            }
            #pragma unroll
            for (int nt = 0; nt < 2; nt++) {
                const uint32_t bo = SWZ128((wn2 + nt * 8 + brow) * 128 + kb + bhalf);
                ldmx2(kh_[nt], smb + KVH_OFF + bo);
                ldmx2(kl_[nt], smb + KVL_OFF + bo);
            }
            #pragma unroll
            for (int mt = 0; mt < 2; mt++)
                #pragma unroll
                for (int nt = 0; nt < 2; nt++) {
                    mma_bf16(sacc[kc][mt][nt], qh_[mt], kh_[nt]);
                    mma_bf16(sacc[kc][mt][nt], qh_[mt], kl_[nt]);
                    mma_bf16(sacc[kc][mt][nt], ql_[mt], kh_[nt]);
                }
        }
    }

    #pragma unroll
    for (int kc = 0; kc < 3; kc++)
        #pragma unroll
        for (int mt = 0; mt < 2; mt++)
            #pragma unroll
            for (int nt = 0; nt < 2; nt++)
                #pragma unroll
                for (int j = 0; j < 4; j++) {
                    const int row = wm2 + mt * 16 + (lane >> 2) + (j >> 1) * 8;
                    const int col = kc * 64 + wn2 + nt * 8 + 2 * (lane & 3) + (j & 1);
                    const int t = t0 + row;
                    const int s = t0 - 64 + col;
                    int dist = t - s; if (dist < 0) dist = -dist;
                    const bool valid = ((unsigned)s < (unsigned)S_) && (dist <= WHALF);
                    sacc[kc][mt][nt][j] = valid ? sacc[kc][mt][nt][j] * 0.125f : -1e30f;
                }

    float rmax[2][2];
    #pragma unroll
    for (int mt = 0; mt < 2; mt++)
        #pragma unroll
        for (int hf = 0; hf < 2; hf++) {
            float m = -1e30f;
            #pragma unroll
            for (int kc = 0; kc < 3; kc++)
                #pragma unroll
                for (int nt = 0; nt < 2; nt++) {
                    m = fmaxf(m, sacc[kc][mt][nt][hf * 2]);
                    m = fmaxf(m, sacc[kc][mt][nt][hf * 2 + 1]);
                }
            m = fmaxf(m, __shfl_xor_sync(0xffffffffu, m, 1));
            m = fmaxf(m, __shfl_xor_sync(0xffffffffu, m, 2));
            rmax[mt][hf] = m;
        }
    #pragma unroll
    for (int mt = 0; mt < 2; mt++)
        #pragma unroll
        for (int hf = 0; hf < 2; hf++)
            red[(wm2 + mt * 16 + (lane >> 2) + hf * 8) * 4 + wg] = rmax[mt][hf];
    __syncthreads();
    #pragma unroll
    for (int mt = 0; mt < 2; mt++)
        #pragma unroll
        for (int hf = 0; hf < 2; hf++) {
            const int r = wm2 + mt * 16 + (lane >> 2) + hf * 8;
            rmax[mt][hf] = fmaxf(fmaxf(red[r * 4], red[r * 4 + 1]),
                                 fmaxf(red[r * 4 + 2], red[r * 4 + 3]));
        }
    __syncthreads();

    float rsum[2][2];
    #pragma unroll
    for (int mt = 0; mt < 2; mt++)
        #pragma unroll
        for (int hf = 0; hf < 2; hf++) {
            float s = 0.0f;
            #pragma unroll
            for (int kc = 0; kc < 3; kc++)
                #pragma unroll
                for (int nt = 0; nt < 2; nt++)
                    #pragma unroll
                    for (int e = 0; e < 2; e++) {
                        float p = __expf(sacc[kc][mt][nt][hf * 2 + e] - rmax[mt][hf]);
                        sacc[kc][mt][nt][hf * 2 + e] = p;
                        s += p;
                    }
            s += __shfl_xor_sync(0xffffffffu, s, 1);
            s += __shfl_xor_sync(0xffffffffu, s, 2);
            rsum[mt][hf] = s;
        }
    #pragma unroll
    for (int mt = 0; mt < 2; mt++)
        #pragma unroll
        for (int hf = 0; hf < 2; hf++)
            red[(wm2 + mt * 16 + (lane >> 2) + hf * 8) * 4 + wg] = rsum[mt][hf];
    __syncthreads();
    #pragma unroll
    for (int mt = 0; mt < 2; mt++)
        #pragma unroll
        for (int hf = 0; hf < 2; hf++) {
            const int r = wm2 + mt * 16 + (lane >> 2) + hf * 8;
            rsum[mt][hf] = 1.0f / (red[r * 4] + red[r * 4 + 1] +
                                   red[r * 4 + 2] + red[r * 4 + 3]);
        }

    #pragma unroll
    for (int kc = 0; kc < 3; kc++)
        #pragma unroll
        for (int mt = 0; mt < 2; mt++)
            #pragma unroll
            for (int nt = 0; nt < 2; nt++)
                #pragma unroll
                for (int hf = 0; hf < 2; hf++) {
                    const int row = wm2 + mt * 16 + (lane >> 2) + hf * 8;
                    const int col = kc * 64 + wn2 + nt * 8 + 2 * (lane & 3);
                    float p0 = sacc[kc][mt][nt][hf * 2]     * rsum[mt][hf];
                    float p1 = sacc[kc][mt][nt][hf * 2 + 1] * rsum[mt][hf];
                    __nv_bfloat16 h0 = bhi(p0), h1 = bhi(p1);
                    __nv_bfloat162 ph2(h0, h1);
                    __nv_bfloat162 pl2(bhi(p0 - __bfloat162float(h0)),
                                       bhi(p1 - __bfloat162float(h1)));
                    *(__nv_bfloat162*)(sm + PH_OFF + row * P_PITCH + col * 2) = ph2;
                    *(__nv_bfloat162*)(sm + PL_OFF + row * P_PITCH + col * 2) = pl2;
                }

    const int wn2v = wg * 16;
    float oacc[2][2][4] = {};
    for (int kc = 0; kc < 3; kc++) {
        const int s0 = t0 - 64 + kc * 64;
        __syncthreads();
        #pragma unroll
        for (int t = 0; t < 2; t++) {
            const int seg = tid + t * 256;
            const int row = seg >> 3, sc = seg & 7;
            const int s = s0 + row;
            int4 vh = make_int4(0, 0, 0, 0), vl = make_int4(0, 0, 0, 0);
            if ((unsigned)s < (unsigned)S_) {
                const size_t g = ((size_t)(b * S_ + s)) * HID_ + h * 64 + sc * 8;
                vh = *(const int4*)(gVh + g);
                vl = *(const int4*)(gVl + g);
            }
            const uint32_t off = SWZ128((uint32_t)(row * 128 + sc * 16));
            *(int4*)(sm + KVH_OFF + off) = vh;
            *(int4*)(sm + KVL_OFF + off) = vl;
        }
        __syncthreads();

        #pragma unroll
        for (int ks = 0; ks < 4; ks++) {
            uint32_t pa_h[2][4], pa_l[2][4], vh_[2][2], vl_[2][2];
            #pragma unroll
            for (int mt = 0; mt < 2; mt++) {
                const uint32_t ao = (uint32_t)((wm2 + mt * 16 + arow) * P_PITCH
                                               + kc * 128 + ks * 32 + ahalf);
                ldmx4(pa_h[mt], smb + PH_OFF + ao);
                ldmx4(pa_l[mt], smb + PL_OFF + ao);
            }
            const int krow = ks * 16 + arow;
            #pragma unroll
            for (int nt = 0; nt < 2; nt++) {
                const uint32_t bo = SWZ128((uint32_t)(krow * 128
                                           + (wn2v + nt * 8) * 2));
                ldmx2t(vh_[nt], smb + KVH_OFF + bo);
                ldmx2t(vl_[nt], smb + KVL_OFF + bo);
            }
            #pragma unroll
            for (int mt = 0; mt < 2; mt++)
                #pragma unroll
                for (int nt = 0; nt < 2; nt++) {
                    mma_bf16(oacc[mt][nt], pa_h[mt], vh_[nt]);
                    mma_bf16(oacc[mt][nt], pa_h[mt], vl_[nt]);
                    mma_bf16(oacc[mt][nt], pa_l[mt], vh_[nt]);
                }
        }
    }

    // ---- epilogue: stage O, then convert to fp16 gAh (hi only) ----
    __syncthreads();
    float* stage = (float*)(sm + PH_OFF);   // [64][68]
    #pragma unroll
    for (int mt = 0; mt < 2; mt++)
        #pragma unroll
        for (int nt = 0; nt < 2; nt++) {
            const int r = wm2 + mt * 16 + (lane >> 2);
            const int c = wn2v + nt * 8 + 2 * (lane & 3);
            *(float2*)&stage[r * 68 + c] = make_float2(oacc[mt][nt][0], oacc[mt][nt][1]);
            *(float2*)&stage[(r + 8) * 68 + c] = make_float2(oacc[mt][nt][2], oacc[mt][nt][3]);
        }
    __syncthreads();
    {
        const int row = tid >> 2, q4 = tid & 3;
        const size_t base = ((size_t)(b * S_ + t0 + row)) * HID_ + h * 64 + q4 * 16;
        const float* sp = &stage[row * 68 + q4 * 16];
        __half2 hbuf[8];
        #pragma unroll
        for (int e = 0; e < 8; e++)
            hbuf[e] = __floats2half2_rn(sp[2 * e], sp[2 * e + 1]);
        *(int4*)(gAh + base)     = *(int4*)&hbuf[0];
        *(int4*)(gAh + base + 8) = *(int4*)&hbuf[4];
    }
}

// ---------------------------------------------------------------------------
extern "C" void kernel_launch(void* const* d_in, const int* in_sizes, int n_in,
                              void* d_out, int out_size) {
    const float* hidden = (const float*)d_in[0];
    const float* Wq     = (const float*)d_in[1];
    const float* Wo     = (const float*)d_in[2];
    float* out = (float*)d_out;
    (void)in_sizes; (void)n_in; (void)out_size;

    cudaFuncSetAttribute(gemm_mma<0>,
                         cudaFuncAttributeMaxDynamicSharedMemorySize, GT_SMEM);
    cudaFuncSetAttribute(gemm_mma<1>,
                         cudaFuncAttributeMaxDynamicSharedMemorySize, GT_SMEM);
    cudaFuncSetAttribute(attn_mma,
                         cudaFuncAttributeMaxDynamicSharedMemorySize, AT_SMEM);

    split_f16<0><<<(M_ * HID_ / 4 + 255) / 256, 256>>>(hidden, M_ * HID_);
    split_f16<1><<<(HID_ * HID_ / 4 + 255) / 256, 256>>>(Wq, HID_ * HID_);
    split_f16<2><<<(HID_ * HID_ / 4 + 255) / 256, 256>>>(Wo, HID_ * HID_);

    dim3 gemm_grid(HID_ / 128, M_ / 64);    // (6, 64) = 384 CTAs, 256 thr each
    gemm_mma<0><<<gemm_grid, 256, GT_SMEM>>>(nullptr);

    dim3 attn_grid(S_ / 64, B_ * NH_);
    attn_mma<<<attn_grid, 256, AT_SMEM>>>();   // writes fp16 gAh for gemm<1>

    gemm_mma<1><<<gemm_grid, 256, GT_SMEM>>>(out);
}

// round 15
// speedup vs baseline: 1.4535x; 1.0230x over previous
#include <cuda_runtime.h>
#include <cuda_bf16.h>
#include <cuda_fp16.h>
#include <math.h>
#include <stdint.h>

#define B_    2
#define S_    2048
#define HID_  768
#define NH_   12
#define HD_   64
#define M_    (B_ * S_)          // 4096 rows
#define WHALF 64                 // WINDOW/2

// ---------------- device scratch (no allocations allowed) ------------------
// fp16 operands for projection GEMMs (2-term scheme: A hi only, W hi+lo)
__device__ __align__(16) __half gAh[M_ * HID_];
__device__ __align__(16) __half gW1h[HID_ * HID_];
__device__ __align__(16) __half gW1l[HID_ * HID_];
__device__ __align__(16) __half gW2h[HID_ * HID_];
__device__ __align__(16) __half gW2l[HID_ * HID_];

// bf16 splits for attention (3-term, written by gemm<0> epilogue)
__device__ __align__(16) __nv_bfloat16 gKh[M_ * HID_];  // q_rot hi (= k)
__device__ __align__(16) __nv_bfloat16 gKl[M_ * HID_];  // q_rot lo
__device__ __align__(16) __nv_bfloat16 gVh[M_ * HID_];  // v hi
__device__ __align__(16) __nv_bfloat16 gVl[M_ * HID_];  // v lo

// persistent-GEMM tile counters (reset by split_all each launch/replay)
__device__ unsigned int gTileCtr[2];

// ---------------- PTX helpers (baseline ISA only) --------------------------
__device__ __forceinline__ uint32_t smem_u32(const void* p) {
    uint32_t a;
    asm("{ .reg .u64 t; cvta.to.shared.u64 t, %1; cvt.u32.u64 %0, t; }"
        : "=r"(a) : "l"(p));
    return a;
}
__device__ __forceinline__ void ldmx4(uint32_t r[4], uint32_t addr) {
    asm volatile("ldmatrix.sync.aligned.m8n8.x4.shared.b16 {%0,%1,%2,%3}, [%4];"
                 : "=r"(r[0]), "=r"(r[1]), "=r"(r[2]), "=r"(r[3]) : "r"(addr));
}
__device__ __forceinline__ void ldmx2(uint32_t r[2], uint32_t addr) {
    asm volatile("ldmatrix.sync.aligned.m8n8.x2.shared.b16 {%0,%1}, [%2];"
                 : "=r"(r[0]), "=r"(r[1]) : "r"(addr));
}
__device__ __forceinline__ void ldmx2t(uint32_t r[2], uint32_t addr) {
    asm volatile("ldmatrix.sync.aligned.m8n8.x2.trans.shared.b16 {%0,%1}, [%2];"
                 : "=r"(r[0]), "=r"(r[1]) : "r"(addr));
}
__device__ __forceinline__ void mma_bf16(float c[4], const uint32_t a[4],
                                         const uint32_t b[2]) {
    asm volatile(
        "mma.sync.aligned.m16n8k16.row.col.f32.bf16.bf16.f32 "
        "{%0,%1,%2,%3}, {%4,%5,%6,%7}, {%8,%9}, {%0,%1,%2,%3};"
        : "+f"(c[0]), "+f"(c[1]), "+f"(c[2]), "+f"(c[3])
        : "r"(a[0]), "r"(a[1]), "r"(a[2]), "r"(a[3]), "r"(b[0]), "r"(b[1]));
}
__device__ __forceinline__ void mma_f16(float c[4], const uint32_t a[4],
                                        const uint32_t b[2]) {
    asm volatile(
        "mma.sync.aligned.m16n8k16.row.col.f32.f16.f16.f32 "
        "{%0,%1,%2,%3}, {%4,%5,%6,%7}, {%8,%9}, {%0,%1,%2,%3};"
        : "+f"(c[0]), "+f"(c[1]), "+f"(c[2]), "+f"(c[3])
        : "r"(a[0]), "r"(a[1]), "r"(a[2]), "r"(a[3]), "r"(b[0]), "r"(b[1]));
}
__device__ __forceinline__ void cp16(uint32_t dst, const void* src) {
    asm volatile("cp.async.cg.shared.global [%0], [%1], 16;"
                 :: "r"(dst), "l"(src));
}
#define CP_COMMIT() asm volatile("cp.async.commit_group;" ::: "memory")
#define CP_WAIT1()  asm volatile("cp.async.wait_group 1;" ::: "memory")

#define SWZ64(off)  ((off) ^ (((off) >> 3) & 0x30))
#define SWZ128(off) ((off) ^ (((off) >> 3) & 0x70))

__device__ __forceinline__ __nv_bfloat16 bhi(float x) { return __float2bfloat16(x); }

// ---------------------------------------------------------------------------
// merged split kernel: resets tile counters, then converts
//   region 0: hidden -> gAh (fp16 hi only)          [3072 blocks]
//   region 1: Wq     -> gW1h + gW1l                  [576 blocks]
//   region 2: Wo     -> gW2h + gW2l                  [576 blocks]
// ---------------------------------------------------------------------------
#define NB_H ((M_ * HID_) / 1024)       // 3072
#define NB_W ((HID_ * HID_) / 1024)     // 576

__global__ __launch_bounds__(256)
void split_all(const float* __restrict__ hidden,
               const float* __restrict__ Wq,
               const float* __restrict__ Wo) {
    if (blockIdx.x == 0 && threadIdx.x == 0) {
        gTileCtr[0] = 0;
        gTileCtr[1] = 0;
    }
    const int b = blockIdx.x;
    if (b < NB_H) {
        const int i = (b * 256 + threadIdx.x) * 4;
        float4 v = *(const float4*)(hidden + i);
        __half2 h01 = __floats2half2_rn(v.x, v.y);
        __half2 h23 = __floats2half2_rn(v.z, v.w);
        *(__half2*)(gAh + i)     = h01;
        *(__half2*)(gAh + i + 2) = h23;
        return;
    }
    const bool isW1 = (b < NB_H + NB_W);
    const float* __restrict__ src = isW1 ? Wq : Wo;
    __half* __restrict__ hi = isW1 ? gW1h : gW2h;
    __half* __restrict__ lo = isW1 ? gW1l : gW2l;
    const int bb = isW1 ? (b - NB_H) : (b - NB_H - NB_W);
    const int i = (bb * 256 + threadIdx.x) * 4;
    float4 v = *(const float4*)(src + i);
    __half h0 = __float2half(v.x), h1 = __float2half(v.y);
    __half h2 = __float2half(v.z), h3 = __float2half(v.w);
    *(__half2*)(hi + i)     = __half2(h0, h1);
    *(__half2*)(hi + i + 2) = __half2(h2, h3);
    __half l0 = __float2half(v.x - __half2float(h0));
    __half l1 = __float2half(v.y - __half2float(h1));
    __half l2 = __float2half(v.z - __half2float(h2));
    __half l3 = __float2half(v.w - __half2float(h3));
    *(__half2*)(lo + i)     = __half2(l0, l1);
    *(__half2*)(lo + i + 2) = __half2(l2, l3);
}

// ---------------------------------------------------------------------------
// PERSISTENT pipelined HMMA GEMM, fp16 2-term: C = Ah*Wh + Ah*Wl.
// Tiles 64x128 pulled from a global atomic queue (near-perfect SM balance
// vs static-wave: 88 SMs stuck with a 3rd serialized tile).
// 256 threads = 8 warps 2(m)x4(n), warp tile 32x32; 2 CTA/SM.
// K chunks of 32, 3-stage cp.async pipeline.
// MODE 0: epilogue = RoPE + bf16 splits -> gKh/gKl, gVh/gVl.
// MODE 1: epilogue = fp32 store to out.
// ---------------------------------------------------------------------------
#define A_TILE_B  4096                      // 64 rows x 64 B
#define W_TILE_B  8192                      // 128 rows x 64 B
#define STAGE_B   (A_TILE_B + 2 * W_TILE_B) // 20480
#define STAGE_PITCH 132
#define GT_SMEM (1024 + 3 * STAGE_B + 16)   // + tile-idx broadcast slot
#define IDX_OFF (1024 + 3 * STAGE_B)
#define NCHUNK (HID_ / 32)                  // 24
#define NTILES ((HID_ / 128) * (M_ / 64))   // 384
#define GEMM_GRID 304                       // >= 2 * num SMs

template<int MODE>
__global__ __launch_bounds__(256, 2)
void gemm_mma(float* __restrict__ out) {
    extern __shared__ __align__(1024) char sm[];
    const uint32_t smb = smem_u32(sm);
    int* tslot = (int*)(sm + IDX_OFF);

    const int tid = threadIdx.x;
    const int wid = tid >> 5, lane = tid & 31;
    const int wm = (wid >> 2) * 32;       // warp m offset (0/32)
    const int wn = (wid & 3) * 32;        // warp n offset (0/32/64/96)

    const __half* __restrict__ Bh = (MODE == 0) ? gW1h : gW2h;
    const __half* __restrict__ Bl = (MODE == 0) ? gW1l : gW2l;

    // lane-static pieces
    const int lrow = tid >> 2;            // 0..63
    const int lseg = tid & 3;
    const uint32_t sa  = SWZ64((uint32_t)(lrow * 64 + lseg * 16));
    const uint32_t sw0 = sa;
    const uint32_t sw1 = SWZ64((uint32_t)((lrow + 64) * 64 + lseg * 16));
    const int arow = lane & 15;
    const int ahalf = (lane >> 4) << 4;
    const int brow = lane & 7;
    const int bhalf = ((lane >> 3) & 1) << 4;

    for (;;) {
        if (tid == 0)
            *tslot = (int)atomicAdd(&gTileCtr[MODE], 1u);
        __syncthreads();
        const int t = *tslot;
        if (t >= NTILES) break;
        const int n0 = (t % (HID_ / 128)) * 128;
        const int m0 = (t / (HID_ / 128)) * 64;

        const size_t gAr  = (size_t)(m0 + lrow) * HID_ + lseg * 8;
        const size_t gWr0 = (size_t)(n0 + lrow) * HID_ + lseg * 8;
        const size_t gWr1 = (size_t)(n0 + lrow + 64) * HID_ + lseg * 8;

        #define LOAD_CHUNK(cc, st)                                            \
        {                                                                     \
            const int k0_ = (cc) * 32;                                        \
            const uint32_t s_ = smb + 1024 + (st) * STAGE_B;                  \
            cp16(s_ + sa, gAh + gAr + k0_);                                   \
            cp16(s_ + A_TILE_B + sw0,            Bh + gWr0 + k0_);            \
            cp16(s_ + A_TILE_B + sw1,            Bh + gWr1 + k0_);            \
            cp16(s_ + A_TILE_B + W_TILE_B + sw0, Bl + gWr0 + k0_);            \
            cp16(s_ + A_TILE_B + W_TILE_B + sw1, Bl + gWr1 + k0_);            \
        }

        float acc[2][4][4] = {};

        LOAD_CHUNK(0, 0); CP_COMMIT();
        LOAD_CHUNK(1, 1); CP_COMMIT();

        int st = 0;
        for (int c = 0; c < NCHUNK; c++) {
            const uint32_t uA  = smb + 1024 + st * STAGE_B;
            const uint32_t uWh = uA + A_TILE_B;
            const uint32_t uWl = uA + A_TILE_B + W_TILE_B;

            CP_WAIT1();
            __syncthreads();

            if (c + 2 < NCHUNK) {
                const int st2 = (st + 2) % 3;
                LOAD_CHUNK(c + 2, st2);
            }
            CP_COMMIT();

            #pragma unroll
            for (int ks = 0; ks < 2; ks++) {
                const int kb = ks * 32;
                uint32_t ah[2][4], bh2[4][2], bl2[4][2];
                #pragma unroll
                for (int mt = 0; mt < 2; mt++) {
                    const int r = wm + mt * 16 + arow;
                    ldmx4(ah[mt], uA + SWZ64(r * 64 + kb + ahalf));
                }
                #pragma unroll
                for (int nt = 0; nt < 4; nt++) {
                    const int r = wn + nt * 8 + brow;
                    const uint32_t off = SWZ64(r * 64 + kb + bhalf);
                    ldmx2(bh2[nt], uWh + off);
                    ldmx2(bl2[nt], uWl + off);
                }
                #pragma unroll
                for (int mt = 0; mt < 2; mt++)
                    #pragma unroll
                    for (int nt = 0; nt < 4; nt++)
                        mma_f16(acc[mt][nt], ah[mt], bh2[nt]);
                #pragma unroll
                for (int mt = 0; mt < 2; mt++)
                    #pragma unroll
                    for (int nt = 0; nt < 4; nt++)
                        mma_f16(acc[mt][nt], ah[mt], bl2[nt]);
            }
            st = (st + 1) % 3;
        }
        #undef LOAD_CHUNK
        __syncthreads();

        // ---- epilogue: stage C in smem [64][132] fp32 ----
        float* stage = (float*)sm;
        #pragma unroll
        for (int mt = 0; mt < 2; mt++)
            #pragma unroll
            for (int nt = 0; nt < 4; nt++) {
                const int r = wm + mt * 16 + (lane >> 2);
                const int cc = wn + nt * 8 + 2 * (lane & 3);
                *(float2*)&stage[r * STAGE_PITCH + cc] =
                    make_float2(acc[mt][nt][0], acc[mt][nt][1]);
                *(float2*)&stage[(r + 8) * STAGE_PITCH + cc] =
                    make_float2(acc[mt][nt][2], acc[mt][nt][3]);
            }
        __syncthreads();

        const int row = tid >> 2;            // 0..63
        const int sub = tid & 3;
        const int m = m0 + row;
        if (MODE == 0) {
            const int hh = sub >> 1, q = sub & 1;
            const float* srow = &stage[row * STAGE_PITCH + hh * 64 + q * 16];
            const float pos = (float)(m & (S_ - 1));
            float vb[32], rb[32];   // [0..15] lo cols, [16..31] hi cols
            #pragma unroll
            for (int j = 0; j < 16; j++) {
                const int d = q * 16 + j;
                const float qlo = srow[j];
                const float qhi = srow[j + 32];
                const float inv = exp2f((float)d * -0.41524101186920654f);
                float sn, cs;
                sincosf(pos * inv, &sn, &cs);
                vb[j] = qlo;          vb[16 + j] = qhi;
                rb[j] = qlo * cs - qhi * sn;
                rb[16 + j] = qhi * cs + qlo * sn;
            }
            const size_t base = (size_t)m * HID_ + n0 + hh * 64 + q * 16;
            #pragma unroll
            for (int half = 0; half < 2; half++) {
                const size_t gb = base + half * 32;
                const float* vv = &vb[half * 16];
                const float* rr = &rb[half * 16];
                __nv_bfloat162 kh4[8], kl4[8], vh4[8], vl4[8];
                #pragma unroll
                for (int e = 0; e < 8; e++) {
                    float v0 = vv[2 * e], v1 = vv[2 * e + 1];
                    float r0 = rr[2 * e], r1 = rr[2 * e + 1];
                    __nv_bfloat16 vh0 = bhi(v0), vh1 = bhi(v1);
                    __nv_bfloat16 rh0 = bhi(r0), rh1 = bhi(r1);
                    vh4[e] = __nv_bfloat162(vh0, vh1);
                    vl4[e] = __nv_bfloat162(bhi(v0 - __bfloat162float(vh0)),
                                            bhi(v1 - __bfloat162float(vh1)));
                    kh4[e] = __nv_bfloat162(rh0, rh1);
                    kl4[e] = __nv_bfloat162(bhi(r0 - __bfloat162float(rh0)),
                                            bhi(r1 - __bfloat162float(rh1)));
                }
                *(int4*)(gKh + gb)     = *(int4*)&kh4[0];
                *(int4*)(gKh + gb + 8) = *(int4*)&kh4[4];
                *(int4*)(gKl + gb)     = *(int4*)&kl4[0];
                *(int4*)(gKl + gb + 8) = *(int4*)&kl4[4];
                *(int4*)(gVh + gb)     = *(int4*)&vh4[0];
                *(int4*)(gVh + gb + 8) = *(int4*)&vh4[4];
                *(int4*)(gVl + gb)     = *(int4*)&vl4[0];
                *(int4*)(gVl + gb + 8) = *(int4*)&vl4[4];
            }
        } else {
            const float* srow = &stage[row * STAGE_PITCH + sub * 32];
            float* op = &out[(size_t)m * HID_ + n0 + sub * 32];
            #pragma unroll
            for (int qq = 0; qq < 8; qq++) {
                float4 f = make_float4(srow[qq * 4], srow[qq * 4 + 1],
                                       srow[qq * 4 + 2], srow[qq * 4 + 3]);
                *(float4*)(op + qq * 4) = f;
            }
        }
        __syncthreads();   // stage overlay safe before next tile's loads
    }
}

// ---------------------------------------------------------------------------
// HMMA sliding-window attention (3-term bf16, unchanged). Epilogue writes
// fp16 hi only -> gAh (gemm<1> is 2-term on the A side).
// ---------------------------------------------------------------------------
#define QH_OFF  0
#define QL_OFF  8192
#define KVH_OFF 16384
#define KVL_OFF 24576
#define PH_OFF  32768
#define PL_OFF  58368
#define RED_OFF 83968
#define AT_SMEM 84992
#define P_PITCH 400

__global__ __launch_bounds__(256, 2)
void attn_mma() {
    extern __shared__ __align__(1024) char sm[];
    const uint32_t smb = smem_u32(sm);

    const int t0 = blockIdx.x * 64;
    const int bh = blockIdx.y;
    const int b = bh / NH_, h = bh % NH_;
    const int tid = threadIdx.x;
    const int wid = tid >> 5, lane = tid & 31;
    const int wm2 = (wid >> 2) * 32;
    const int wg  = wid & 3;
    const int wn2 = wg * 16;

    const int arow = lane & 15;
    const int ahalf = (lane >> 4) << 4;
    const int brow = lane & 7;
    const int bhalf = ((lane >> 3) & 1) << 4;

    float* red = (float*)(sm + RED_OFF);

    #pragma unroll
    for (int t = 0; t < 2; t++) {
        const int seg = tid + t * 256;
        const int row = seg >> 3, sc = seg & 7;
        const size_t g = ((size_t)(b * S_ + t0 + row)) * HID_ + h * 64 + sc * 8;
        const uint32_t off = SWZ128((uint32_t)(row * 128 + sc * 16));
        *(int4*)(sm + QH_OFF + off) = *(const int4*)(gKh + g);
        *(int4*)(sm + QL_OFF + off) = *(const int4*)(gKl + g);
    }

    float sacc[3][2][2][4] = {};
    for (int kc = 0; kc < 3; kc++) {
        const int s0 = t0 - 64 + kc * 64;
        __syncthreads();
        #pragma unroll
        for (int t = 0; t < 2; t++) {
            const int seg = tid + t * 256;
            const int row = seg >> 3, sc = seg & 7;
            const int s = s0 + row;
            int4 vh = make_int4(0, 0, 0, 0), vl = make_int4(0, 0, 0, 0);
            if ((unsigned)s < (unsigned)S_) {
                const size_t g = ((size_t)(b * S_ + s)) * HID_ + h * 64 + sc * 8;
                vh = *(const int4*)(gKh + g);
                vl = *(const int4*)(gKl + g);
            }
            const uint32_t off = SWZ128((uint32_t)(row * 128 + sc * 16));
            *(int4*)(sm + KVH_OFF + off) = vh;
            *(int4*)(sm + KVL_OFF + off) = vl;
        }
        __syncthreads();

        #pragma unroll
        for (int ks = 0; ks < 4; ks++) {
            const int kb = ks * 32;
            uint32_t qh_[2][4], ql_[2][4], kh_[2][2], kl_[2][2];
            #pragma unroll
            for (int mt = 0; mt < 2; mt++) {
                const uint32_t ao = SWZ128((wm2 + mt * 16 + arow) * 128 + kb + ahalf);
                ldmx4(qh_[mt], smb + QH_OFF + ao);
                ldmx4(ql_[mt], smb + QL_OFF + ao);
            }
            #pragma unroll
            for (int nt = 0; nt < 2; nt++) {
                const uint32_t bo = SWZ128((wn2 + nt * 8 + brow) * 128 + kb + bhalf);
                ldmx2(kh_[nt], smb + KVH_OFF + bo);
                ldmx2(kl_[nt], smb + KVL_OFF + bo);
            }
            #pragma unroll
            for (int mt = 0; mt < 2; mt++)
                #pragma unroll
                for (int nt = 0; nt < 2; nt++) {
                    mma_bf16(sacc[kc][mt][nt], qh_[mt], kh_[nt]);
                    mma_bf16(sacc[kc][mt][nt], qh_[mt], kl_[nt]);
                    mma_bf16(sacc[kc][mt][nt], ql_[mt], kh_[nt]);
                }
        }
    }

    #pragma unroll
    for (int kc = 0; kc < 3; kc++)
        #pragma unroll
        for (int mt = 0; mt < 2; mt++)
            #pragma unroll
            for (int nt = 0; nt < 2; nt++)
                #pragma unroll
                for (int j = 0; j < 4; j++) {
                    const int row = wm2 + mt * 16 + (lane >> 2) + (j >> 1) * 8;
                    const int col = kc * 64 + wn2 + nt * 8 + 2 * (lane & 3) + (j & 1);
                    const int t = t0 + row;
                    const int s = t0 - 64 + col;
                    int dist = t - s; if (dist < 0) dist = -dist;
                    const bool valid = ((unsigned)s < (unsigned)S_) && (dist <= WHALF);
                    sacc[kc][mt][nt][j] = valid ? sacc[kc][mt][nt][j] * 0.125f : -1e30f;
                }

    float rmax[2][2];
    #pragma unroll
    for (int mt = 0; mt < 2; mt++)
        #pragma unroll
        for (int hf = 0; hf < 2; hf++) {
            float m = -1e30f;
            #pragma unroll
            for (int kc = 0; kc < 3; kc++)
                #pragma unroll
                for (int nt = 0; nt < 2; nt++) {
                    m = fmaxf(m, sacc[kc][mt][nt][hf * 2]);
                    m = fmaxf(m, sacc[kc][mt][nt][hf * 2 + 1]);
                }
            m = fmaxf(m, __shfl_xor_sync(0xffffffffu, m, 1));
            m = fmaxf(m, __shfl_xor_sync(0xffffffffu, m, 2));
            rmax[mt][hf] = m;
        }
    #pragma unroll
    for (int mt = 0; mt < 2; mt++)
        #pragma unroll
        for (int hf = 0; hf < 2; hf++)
            red[(wm2 + mt * 16 + (lane >> 2) + hf * 8) * 4 + wg] = rmax[mt][hf];
    __syncthreads();
    #pragma unroll
    for (int mt = 0; mt < 2; mt++)
        #pragma unroll
        for (int hf = 0; hf < 2; hf++) {
            const int r = wm2 + mt * 16 + (lane >> 2) + hf * 8;
            rmax[mt][hf] = fmaxf(fmaxf(red[r * 4], red[r * 4 + 1]),
                                 fmaxf(red[r * 4 + 2], red[r * 4 + 3]));
        }
    __syncthreads();

    float rsum[2][2];
    #pragma unroll
    for (int mt = 0; mt < 2; mt++)
        #pragma unroll
        for (int hf = 0; hf < 2; hf++) {
            float s = 0.0f;
            #pragma unroll
            for (int kc = 0; kc < 3; kc++)
                #pragma unroll
                for (int nt = 0; nt < 2; nt++)
                    #pragma unroll
                    for (int e = 0; e < 2; e++) {
                        float p = __expf(sacc[kc][mt][nt][hf * 2 + e] - rmax[mt][hf]);
                        sacc[kc][mt][nt][hf * 2 + e] = p;
                        s += p;
                    }
            s += __shfl_xor_sync(0xffffffffu, s, 1);
            s += __shfl_xor_sync(0xffffffffu, s, 2);
            rsum[mt][hf] = s;
        }
    #pragma unroll
    for (int mt = 0; mt < 2; mt++)
        #pragma unroll
        for (int hf = 0; hf < 2; hf++)
            red[(wm2 + mt * 16 + (lane >> 2) + hf * 8) * 4 + wg] = rsum[mt][hf];
    __syncthreads();
    #pragma unroll
    for (int mt = 0; mt < 2; mt++)
        #pragma unroll
        for (int hf = 0; hf < 2; hf++) {
            const int r = wm2 + mt * 16 + (lane >> 2) + hf * 8;
            rsum[mt][hf] = 1.0f / (red[r * 4] + red[r * 4 + 1] +
                                   red[r * 4 + 2] + red[r * 4 + 3]);
        }

    #pragma unroll
    for (int kc = 0; kc < 3; kc++)
        #pragma unroll
        for (int mt = 0; mt < 2; mt++)
            #pragma unroll
            for (int nt = 0; nt < 2; nt++)
                #pragma unroll
                for (int hf = 0; hf < 2; hf++) {
                    const int row = wm2 + mt * 16 + (lane >> 2) + hf * 8;
                    const int col = kc * 64 + wn2 + nt * 8 + 2 * (lane & 3);
                    float p0 = sacc[kc][mt][nt][hf * 2]     * rsum[mt][hf];
                    float p1 = sacc[kc][mt][nt][hf * 2 + 1] * rsum[mt][hf];
                    __nv_bfloat16 h0 = bhi(p0), h1 = bhi(p1);
                    __nv_bfloat162 ph2(h0, h1);
                    __nv_bfloat162 pl2(bhi(p0 - __bfloat162float(h0)),
                                       bhi(p1 - __bfloat162float(h1)));
                    *(__nv_bfloat162*)(sm + PH_OFF + row * P_PITCH + col * 2) = ph2;
                    *(__nv_bfloat162*)(sm + PL_OFF + row * P_PITCH + col * 2) = pl2;
                }

    const int wn2v = wg * 16;
    float oacc[2][2][4] = {};
    for (int kc = 0; kc < 3; kc++) {
        const int s0 = t0 - 64 + kc * 64;
        __syncthreads();
        #pragma unroll
        for (int t = 0; t < 2; t++) {
            const int seg = tid + t * 256;
            const int row = seg >> 3, sc = seg & 7;
            const int s = s0 + row;
            int4 vh = make_int4(0, 0, 0, 0), vl = make_int4(0, 0, 0, 0);
            if ((unsigned)s < (unsigned)S_) {
                const size_t g = ((size_t)(b * S_ + s)) * HID_ + h * 64 + sc * 8;
                vh = *(const int4*)(gVh + g);
                vl = *(const int4*)(gVl + g);
            }
            const uint32_t off = SWZ128((uint32_t)(row * 128 + sc * 16));
            *(int4*)(sm + KVH_OFF + off) = vh;
            *(int4*)(sm + KVL_OFF + off) = vl;
        }
        __syncthreads();

        #pragma unroll
        for (int ks = 0; ks < 4; ks++) {
            uint32_t pa_h[2][4], pa_l[2][4], vh_[2][2], vl_[2][2];
            #pragma unroll
            for (int mt = 0; mt < 2; mt++) {
                const uint32_t ao = (uint32_t)((wm2 + mt * 16 + arow) * P_PITCH
                                               + kc * 128 + ks * 32 + ahalf);
                ldmx4(pa_h[mt], smb + PH_OFF + ao);
                ldmx4(pa_l[mt], smb + PL_OFF + ao);
            }
            const int krow = ks * 16 + arow;
            #pragma unroll
            for (int nt = 0; nt < 2; nt++) {
                const uint32_t bo = SWZ128((uint32_t)(krow * 128
                                           + (wn2v + nt * 8) * 2));
                ldmx2t(vh_[nt], smb + KVH_OFF + bo);
                ldmx2t(vl_[nt], smb + KVL_OFF + bo);
            }
            #pragma unroll
            for (int mt = 0; mt < 2; mt++)
                #pragma unroll
                for (int nt = 0; nt < 2; nt++) {
                    mma_bf16(oacc[mt][nt], pa_h[mt], vh_[nt]);
                    mma_bf16(oacc[mt][nt], pa_h[mt], vl_[nt]);
                    mma_bf16(oacc[mt][nt], pa_l[mt], vh_[nt]);
                }
        }
    }

    // ---- epilogue: stage O, then convert to fp16 gAh (hi only) ----
    __syncthreads();
    float* stage = (float*)(sm + PH_OFF);   // [64][68]
    #pragma unroll
    for (int mt = 0; mt < 2; mt++)
        #pragma unroll
        for (int nt = 0; nt < 2; nt++) {
            const int r = wm2 + mt * 16 + (lane >> 2);
            const int c = wn2v + nt * 8 + 2 * (lane & 3);
            *(float2*)&stage[r * 68 + c] = make_float2(oacc[mt][nt][0], oacc[mt][nt][1]);
            *(float2*)&stage[(r + 8) * 68 + c] = make_float2(oacc[mt][nt][2], oacc[mt][nt][3]);
        }
    __syncthreads();
    {
        const int row = tid >> 2, q4 = tid & 3;
        const size_t base = ((size_t)(b * S_ + t0 + row)) * HID_ + h * 64 + q4 * 16;
        const float* sp = &stage[row * 68 + q4 * 16];
        __half2 hbuf[8];
        #pragma unroll
        for (int e = 0; e < 8; e++)
            hbuf[e] = __floats2half2_rn(sp[2 * e], sp[2 * e + 1]);
        *(int4*)(gAh + base)     = *(int4*)&hbuf[0];
        *(int4*)(gAh + base + 8) = *(int4*)&hbuf[4];
    }
}

// ---------------------------------------------------------------------------
extern "C" void kernel_launch(void* const* d_in, const int* in_sizes, int n_in,
                              void* d_out, int out_size) {
    const float* hidden = (const float*)d_in[0];
    const float* Wq     = (const float*)d_in[1];
    const float* Wo     = (const float*)d_in[2];
    float* out = (float*)d_out;
    (void)in_sizes; (void)n_in; (void)out_size;

    cudaFuncSetAttribute(gemm_mma<0>,
                         cudaFuncAttributeMaxDynamicSharedMemorySize, GT_SMEM);
    cudaFuncSetAttribute(gemm_mma<1>,
                         cudaFuncAttributeMaxDynamicSharedMemorySize, GT_SMEM);
    cudaFuncSetAttribute(attn_mma,
                         cudaFuncAttributeMaxDynamicSharedMemorySize, AT_SMEM);

    // one merged split kernel: resets tile counters + all fp16 converts
    split_all<<<NB_H + 2 * NB_W, 256>>>(hidden, Wq, Wo);

    gemm_mma<0><<<GEMM_GRID, 256, GT_SMEM>>>(nullptr);

    dim3 attn_grid(S_ / 64, B_ * NH_);
    attn_mma<<<attn_grid, 256, AT_SMEM>>>();   // writes fp16 gAh for gemm<1>

    gemm_mma<1><<<GEMM_GRID, 256, GT_SMEM>>>(out);
}

// round 16
// speedup vs baseline: 1.4702x; 1.0115x over previous
#include <cuda_runtime.h>
#include <cuda_bf16.h>
#include <cuda_fp16.h>
#include <math.h>
#include <stdint.h>

#define B_    2
#define S_    2048
#define HID_  768
#define NH_   12
#define HD_   64
#define M_    (B_ * S_)          // 4096 rows
#define WHALF 64                 // WINDOW/2

// ---------------- device scratch (no allocations allowed) ------------------
// fp16 operands for projection GEMMs (2-term scheme: A hi only, W hi+lo)
__device__ __align__(16) __half gAh[M_ * HID_];
__device__ __align__(16) __half gW1h[HID_ * HID_];
__device__ __align__(16) __half gW1l[HID_ * HID_];
__device__ __align__(16) __half gW2h[HID_ * HID_];
__device__ __align__(16) __half gW2l[HID_ * HID_];

// fp16 splits for attention (written by gemm<0> epilogue)
__device__ __align__(16) __half gKh[M_ * HID_];  // q_rot hi (= k = q)
__device__ __align__(16) __half gKl[M_ * HID_];  // q_rot lo
__device__ __align__(16) __half gVh[M_ * HID_];  // v hi
__device__ __align__(16) __half gVl[M_ * HID_];  // v lo

// persistent tile counters: [0]=gemm0, [1]=gemm1, [2]=attn (reset by split_all)
__device__ unsigned int gTileCtr[3];

// ---------------- PTX helpers (baseline ISA only) --------------------------
__device__ __forceinline__ uint32_t smem_u32(const void* p) {
    uint32_t a;
    asm("{ .reg .u64 t; cvta.to.shared.u64 t, %1; cvt.u32.u64 %0, t; }"
        : "=r"(a) : "l"(p));
    return a;
}
__device__ __forceinline__ void ldmx4(uint32_t r[4], uint32_t addr) {
    asm volatile("ldmatrix.sync.aligned.m8n8.x4.shared.b16 {%0,%1,%2,%3}, [%4];"
                 : "=r"(r[0]), "=r"(r[1]), "=r"(r[2]), "=r"(r[3]) : "r"(addr));
}
__device__ __forceinline__ void ldmx2(uint32_t r[2], uint32_t addr) {
    asm volatile("ldmatrix.sync.aligned.m8n8.x2.shared.b16 {%0,%1}, [%2];"
                 : "=r"(r[0]), "=r"(r[1]) : "r"(addr));
}
__device__ __forceinline__ void ldmx2t(uint32_t r[2], uint32_t addr) {
    asm volatile("ldmatrix.sync.aligned.m8n8.x2.trans.shared.b16 {%0,%1}, [%2];"
                 : "=r"(r[0]), "=r"(r[1]) : "r"(addr));
}
__device__ __forceinline__ void mma_f16(float c[4], const uint32_t a[4],
                                        const uint32_t b[2]) {
    asm volatile(
        "mma.sync.aligned.m16n8k16.row.col.f32.f16.f16.f32 "
        "{%0,%1,%2,%3}, {%4,%5,%6,%7}, {%8,%9}, {%0,%1,%2,%3};"
        : "+f"(c[0]), "+f"(c[1]), "+f"(c[2]), "+f"(c[3])
        : "r"(a[0]), "r"(a[1]), "r"(a[2]), "r"(a[3]), "r"(b[0]), "r"(b[1]));
}
__device__ __forceinline__ void cp16(uint32_t dst, const void* src) {
    asm volatile("cp.async.cg.shared.global [%0], [%1], 16;"
                 :: "r"(dst), "l"(src));
}
#define CP_COMMIT() asm volatile("cp.async.commit_group;" ::: "memory")
#define CP_WAIT1()  asm volatile("cp.async.wait_group 1;" ::: "memory")

#define SWZ64(off)  ((off) ^ (((off) >> 3) & 0x30))
#define SWZ128(off) ((off) ^ (((off) >> 3) & 0x70))

// ---------------------------------------------------------------------------
// merged split kernel: resets tile counters, then converts
//   region 0: hidden -> gAh (fp16 hi only)          [3072 blocks]
//   region 1: Wq     -> gW1h + gW1l                  [576 blocks]
//   region 2: Wo     -> gW2h + gW2l                  [576 blocks]
// ---------------------------------------------------------------------------
#define NB_H ((M_ * HID_) / 1024)       // 3072
#define NB_W ((HID_ * HID_) / 1024)     // 576

__global__ __launch_bounds__(256)
void split_all(const float* __restrict__ hidden,
               const float* __restrict__ Wq,
               const float* __restrict__ Wo) {
    if (blockIdx.x == 0 && threadIdx.x == 0) {
        gTileCtr[0] = 0;
        gTileCtr[1] = 0;
        gTileCtr[2] = 0;
    }
    const int b = blockIdx.x;
    if (b < NB_H) {
        const int i = (b * 256 + threadIdx.x) * 4;
        float4 v = *(const float4*)(hidden + i);
        *(__half2*)(gAh + i)     = __floats2half2_rn(v.x, v.y);
        *(__half2*)(gAh + i + 2) = __floats2half2_rn(v.z, v.w);
        return;
    }
    const bool isW1 = (b < NB_H + NB_W);
    const float* __restrict__ src = isW1 ? Wq : Wo;
    __half* __restrict__ hi = isW1 ? gW1h : gW2h;
    __half* __restrict__ lo = isW1 ? gW1l : gW2l;
    const int bb = isW1 ? (b - NB_H) : (b - NB_H - NB_W);
    const int i = (bb * 256 + threadIdx.x) * 4;
    float4 v = *(const float4*)(src + i);
    __half h0 = __float2half(v.x), h1 = __float2half(v.y);
    __half h2 = __float2half(v.z), h3 = __float2half(v.w);
    *(__half2*)(hi + i)     = __half2(h0, h1);
    *(__half2*)(hi + i + 2) = __half2(h2, h3);
    __half l0 = __float2half(v.x - __half2float(h0));
    __half l1 = __float2half(v.y - __half2float(h1));
    __half l2 = __float2half(v.z - __half2float(h2));
    __half l3 = __float2half(v.w - __half2float(h3));
    *(__half2*)(lo + i)     = __half2(l0, l1);
    *(__half2*)(lo + i + 2) = __half2(l2, l3);
}

// ---------------------------------------------------------------------------
// PERSISTENT pipelined HMMA GEMM, fp16 2-term: C = Ah*Wh + Ah*Wl.
// 64x128 tiles from an atomic queue. 256 threads = 8 warps 2(m)x4(n),
// warp tile 32x32; 2 CTA/SM. K chunks of 32, 3-stage cp.async pipeline.
// MODE 0: epilogue = RoPE + fp16 splits -> gKh/gKl, gVh/gVl.
// MODE 1: epilogue = fp32 store to out.
// ---------------------------------------------------------------------------
#define A_TILE_B  4096                      // 64 rows x 64 B
#define W_TILE_B  8192                      // 128 rows x 64 B
#define STAGE_B   (A_TILE_B + 2 * W_TILE_B) // 20480
#define STAGE_PITCH 132
#define GT_SMEM (1024 + 3 * STAGE_B + 16)
#define IDX_OFF (1024 + 3 * STAGE_B)
#define NCHUNK (HID_ / 32)                  // 24
#define NTILES ((HID_ / 128) * (M_ / 64))   // 384
#define GEMM_GRID 296

template<int MODE>
__global__ __launch_bounds__(256, 2)
void gemm_mma(float* __restrict__ out) {
    extern __shared__ __align__(1024) char sm[];
    const uint32_t smb = smem_u32(sm);
    int* tslot = (int*)(sm + IDX_OFF);

    const int tid = threadIdx.x;
    const int wid = tid >> 5, lane = tid & 31;
    const int wm = (wid >> 2) * 32;
    const int wn = (wid & 3) * 32;

    const __half* __restrict__ Bh = (MODE == 0) ? gW1h : gW2h;
    const __half* __restrict__ Bl = (MODE == 0) ? gW1l : gW2l;

    const int lrow = tid >> 2;
    const int lseg = tid & 3;
    const uint32_t sa  = SWZ64((uint32_t)(lrow * 64 + lseg * 16));
    const uint32_t sw0 = sa;
    const uint32_t sw1 = SWZ64((uint32_t)((lrow + 64) * 64 + lseg * 16));
    const int arow = lane & 15;
    const int ahalf = (lane >> 4) << 4;
    const int brow = lane & 7;
    const int bhalf = ((lane >> 3) & 1) << 4;

    for (;;) {
        if (tid == 0)
            *tslot = (int)atomicAdd(&gTileCtr[MODE], 1u);
        __syncthreads();
        const int t = *tslot;
        if (t >= NTILES) break;
        const int n0 = (t % (HID_ / 128)) * 128;
        const int m0 = (t / (HID_ / 128)) * 64;

        const size_t gAr  = (size_t)(m0 + lrow) * HID_ + lseg * 8;
        const size_t gWr0 = (size_t)(n0 + lrow) * HID_ + lseg * 8;
        const size_t gWr1 = (size_t)(n0 + lrow + 64) * HID_ + lseg * 8;

        #define LOAD_CHUNK(cc, st)                                            \
        {                                                                     \
            const int k0_ = (cc) * 32;                                        \
            const uint32_t s_ = smb + 1024 + (st) * STAGE_B;                  \
            cp16(s_ + sa, gAh + gAr + k0_);                                   \
            cp16(s_ + A_TILE_B + sw0,            Bh + gWr0 + k0_);            \
            cp16(s_ + A_TILE_B + sw1,            Bh + gWr1 + k0_);            \
            cp16(s_ + A_TILE_B + W_TILE_B + sw0, Bl + gWr0 + k0_);            \
            cp16(s_ + A_TILE_B + W_TILE_B + sw1, Bl + gWr1 + k0_);            \
        }

        float acc[2][4][4] = {};

        LOAD_CHUNK(0, 0); CP_COMMIT();
        LOAD_CHUNK(1, 1); CP_COMMIT();

        int st = 0;
        for (int c = 0; c < NCHUNK; c++) {
            const uint32_t uA  = smb + 1024 + st * STAGE_B;
            const uint32_t uWh = uA + A_TILE_B;
            const uint32_t uWl = uA + A_TILE_B + W_TILE_B;

            CP_WAIT1();
            __syncthreads();

            if (c + 2 < NCHUNK) {
                const int st2 = (st + 2) % 3;
                LOAD_CHUNK(c + 2, st2);
            }
            CP_COMMIT();

            #pragma unroll
            for (int ks = 0; ks < 2; ks++) {
                const int kb = ks * 32;
                uint32_t ah[2][4], bh2[4][2], bl2[4][2];
                #pragma unroll
                for (int mt = 0; mt < 2; mt++) {
                    const int r = wm + mt * 16 + arow;
                    ldmx4(ah[mt], uA + SWZ64(r * 64 + kb + ahalf));
                }
                #pragma unroll
                for (int nt = 0; nt < 4; nt++) {
                    const int r = wn + nt * 8 + brow;
                    const uint32_t off = SWZ64(r * 64 + kb + bhalf);
                    ldmx2(bh2[nt], uWh + off);
                    ldmx2(bl2[nt], uWl + off);
                }
                #pragma unroll
                for (int mt = 0; mt < 2; mt++)
                    #pragma unroll
                    for (int nt = 0; nt < 4; nt++)
                        mma_f16(acc[mt][nt], ah[mt], bh2[nt]);
                #pragma unroll
                for (int mt = 0; mt < 2; mt++)
                    #pragma unroll
                    for (int nt = 0; nt < 4; nt++)
                        mma_f16(acc[mt][nt], ah[mt], bl2[nt]);
            }
            st = (st + 1) % 3;
        }
        #undef LOAD_CHUNK
        __syncthreads();

        // ---- epilogue: stage C in smem [64][132] fp32 ----
        float* stage = (float*)sm;
        #pragma unroll
        for (int mt = 0; mt < 2; mt++)
            #pragma unroll
            for (int nt = 0; nt < 4; nt++) {
                const int r = wm + mt * 16 + (lane >> 2);
                const int cc = wn + nt * 8 + 2 * (lane & 3);
                *(float2*)&stage[r * STAGE_PITCH + cc] =
                    make_float2(acc[mt][nt][0], acc[mt][nt][1]);
                *(float2*)&stage[(r + 8) * STAGE_PITCH + cc] =
                    make_float2(acc[mt][nt][2], acc[mt][nt][3]);
            }
        __syncthreads();

        const int row = tid >> 2;
        const int sub = tid & 3;
        const int m = m0 + row;
        if (MODE == 0) {
            const int hh = sub >> 1, q = sub & 1;
            const float* srow = &stage[row * STAGE_PITCH + hh * 64 + q * 16];
            const float pos = (float)(m & (S_ - 1));
            float vb[32], rb[32];   // [0..15] lo cols, [16..31] hi cols
            #pragma unroll
            for (int j = 0; j < 16; j++) {
                const int d = q * 16 + j;
                const float qlo = srow[j];
                const float qhi = srow[j + 32];
                const float inv = exp2f((float)d * -0.41524101186920654f);
                float sn, cs;
                sincosf(pos * inv, &sn, &cs);
                vb[j] = qlo;          vb[16 + j] = qhi;
                rb[j] = qlo * cs - qhi * sn;
                rb[16 + j] = qhi * cs + qlo * sn;
            }
            const size_t base = (size_t)m * HID_ + n0 + hh * 64 + q * 16;
            #pragma unroll
            for (int half = 0; half < 2; half++) {
                const size_t gb = base + half * 32;
                const float* vv = &vb[half * 16];
                const float* rr = &rb[half * 16];
                __half2 kh4[8], kl4[8], vh4[8], vl4[8];
                #pragma unroll
                for (int e = 0; e < 8; e++) {
                    float v0 = vv[2 * e], v1 = vv[2 * e + 1];
                    float r0 = rr[2 * e], r1 = rr[2 * e + 1];
                    __half vh0 = __float2half(v0), vh1 = __float2half(v1);
                    __half rh0 = __float2half(r0), rh1 = __float2half(r1);
                    vh4[e] = __half2(vh0, vh1);
                    vl4[e] = __half2(__float2half(v0 - __half2float(vh0)),
                                     __float2half(v1 - __half2float(vh1)));
                    kh4[e] = __half2(rh0, rh1);
                    kl4[e] = __half2(__float2half(r0 - __half2float(rh0)),
                                     __float2half(r1 - __half2float(rh1)));
                }
                *(int4*)(gKh + gb)     = *(int4*)&kh4[0];
                *(int4*)(gKh + gb + 8) = *(int4*)&kh4[4];
                *(int4*)(gKl + gb)     = *(int4*)&kl4[0];
                *(int4*)(gKl + gb + 8) = *(int4*)&kl4[4];
                *(int4*)(gVh + gb)     = *(int4*)&vh4[0];
                *(int4*)(gVh + gb + 8) = *(int4*)&vh4[4];
                *(int4*)(gVl + gb)     = *(int4*)&vl4[0];
                *(int4*)(gVl + gb + 8) = *(int4*)&vl4[4];
            }
        } else {
            const float* srow = &stage[row * STAGE_PITCH + sub * 32];
            float* op = &out[(size_t)m * HID_ + n0 + sub * 32];
            #pragma unroll
            for (int qq = 0; qq < 8; qq++) {
                float4 f = make_float4(srow[qq * 4], srow[qq * 4 + 1],
                                       srow[qq * 4 + 2], srow[qq * 4 + 3]);
                *(float4*)(op + qq * 4) = f;
            }
        }
        __syncthreads();
    }
}

// ---------------------------------------------------------------------------
// PERSISTENT HMMA sliding-window attention, fp16.
// Scores 2-term: S = Qh*Kh + Qh*Kl. PV 3-term: O = Ph*Vh + Ph*Vl + Pl*Vh.
// Tiles from atomic queue gTileCtr[2]; tile = (bh, t0).
// Epilogue writes fp16 hi only -> gAh (feeds gemm<1>).
// smem: Qh 8KB, KVh 8KB, KVl 8KB, Ph 25.6KB, Pl 25.6KB, red 1KB, idx 16B
// ---------------------------------------------------------------------------
#define QH_OFF   0
#define KVH_OFF  8192
#define KVL_OFF  16384
#define PH_OFF   24576
#define PL_OFF   50176
#define RED_OFF  75776
#define AIDX_OFF 76800
#define AT_SMEM  76832
#define P_PITCH  400
#define NT_AT    ((S_ / 64) * B_ * NH_)   // 768

__global__ __launch_bounds__(256, 2)
void attn_mma() {
    extern __shared__ __align__(1024) char sm[];
    const uint32_t smb = smem_u32(sm);
    int* tslot = (int*)(sm + AIDX_OFF);
    float* red = (float*)(sm + RED_OFF);

    const int tid = threadIdx.x;
    const int wid = tid >> 5, lane = tid & 31;
    const int wm2 = (wid >> 2) * 32;
    const int wg  = wid & 3;
    const int wn2 = wg * 16;

    const int arow = lane & 15;
    const int ahalf = (lane >> 4) << 4;
    const int brow = lane & 7;
    const int bhalf = ((lane >> 3) & 1) << 4;

    for (;;) {
        if (tid == 0)
            *tslot = (int)atomicAdd(&gTileCtr[2], 1u);
        __syncthreads();
        const int tt = *tslot;
        if (tt >= NT_AT) break;
        const int t0 = (tt & 31) * 64;     // 32 q-tiles per (b,h)
        const int bh = tt >> 5;
        const int b = bh / NH_, h = bh % NH_;

        // ---- load Q (hi only) ----
        #pragma unroll
        for (int t = 0; t < 2; t++) {
            const int seg = tid + t * 256;
            const int row = seg >> 3, sc = seg & 7;
            const size_t g = ((size_t)(b * S_ + t0 + row)) * HID_ + h * 64 + sc * 8;
            const uint32_t off = SWZ128((uint32_t)(row * 128 + sc * 16));
            *(int4*)(sm + QH_OFF + off) = *(const int4*)(gKh + g);
        }

        // ---- score phase: 3 key chunks, 2-term fp16 ----
        float sacc[3][2][2][4] = {};
        for (int kc = 0; kc < 3; kc++) {
            const int s0 = t0 - 64 + kc * 64;
            __syncthreads();
            #pragma unroll
            for (int t = 0; t < 2; t++) {
                const int seg = tid + t * 256;
                const int row = seg >> 3, sc = seg & 7;
                const int s = s0 + row;
                int4 vh = make_int4(0, 0, 0, 0), vl = make_int4(0, 0, 0, 0);
                if ((unsigned)s < (unsigned)S_) {
                    const size_t g = ((size_t)(b * S_ + s)) * HID_ + h * 64 + sc * 8;
                    vh = *(const int4*)(gKh + g);
                    vl = *(const int4*)(gKl + g);
                }
                const uint32_t off = SWZ128((uint32_t)(row * 128 + sc * 16));
                *(int4*)(sm + KVH_OFF + off) = vh;
                *(int4*)(sm + KVL_OFF + off) = vl;
            }
            __syncthreads();

            #pragma unroll
            for (int ks = 0; ks < 4; ks++) {
                const int kb = ks * 32;
                uint32_t qh_[2][4], kh_[2][2], kl_[2][2];
                #pragma unroll
                for (int mt = 0; mt < 2; mt++) {
                    const uint32_t ao = SWZ128((wm2 + mt * 16 + arow) * 128 + kb + ahalf);
                    ldmx4(qh_[mt], smb + QH_OFF + ao);
                }
                #pragma unroll
                for (int nt = 0; nt < 2; nt++) {
                    const uint32_t bo = SWZ128((wn2 + nt * 8 + brow) * 128 + kb + bhalf);
                    ldmx2(kh_[nt], smb + KVH_OFF + bo);
                    ldmx2(kl_[nt], smb + KVL_OFF + bo);
                }
                #pragma unroll
                for (int mt = 0; mt < 2; mt++)
                    #pragma unroll
                    for (int nt = 0; nt < 2; nt++) {
                        mma_f16(sacc[kc][mt][nt], qh_[mt], kh_[nt]);
                        mma_f16(sacc[kc][mt][nt], qh_[mt], kl_[nt]);
                    }
            }
        }

        // ---- mask + scale ----
        #pragma unroll
        for (int kc = 0; kc < 3; kc++)
            #pragma unroll
            for (int mt = 0; mt < 2; mt++)
                #pragma unroll
                for (int nt = 0; nt < 2; nt++)
                    #pragma unroll
                    for (int j = 0; j < 4; j++) {
                        const int row = wm2 + mt * 16 + (lane >> 2) + (j >> 1) * 8;
                        const int col = kc * 64 + wn2 + nt * 8 + 2 * (lane & 3) + (j & 1);
                        const int t = t0 + row;
                        const int s = t0 - 64 + col;
                        int dist = t - s; if (dist < 0) dist = -dist;
                        const bool valid = ((unsigned)s < (unsigned)S_) && (dist <= WHALF);
                        sacc[kc][mt][nt][j] = valid ? sacc[kc][mt][nt][j] * 0.125f : -1e30f;
                    }

        // ---- softmax: row max ----
        float rmax[2][2];
        #pragma unroll
        for (int mt = 0; mt < 2; mt++)
            #pragma unroll
            for (int hf = 0; hf < 2; hf++) {
                float m = -1e30f;
                #pragma unroll
                for (int kc = 0; kc < 3; kc++)
                    #pragma unroll
                    for (int nt = 0; nt < 2; nt++) {
                        m = fmaxf(m, sacc[kc][mt][nt][hf * 2]);
                        m = fmaxf(m, sacc[kc][mt][nt][hf * 2 + 1]);
                    }
                m = fmaxf(m, __shfl_xor_sync(0xffffffffu, m, 1));
                m = fmaxf(m, __shfl_xor_sync(0xffffffffu, m, 2));
                rmax[mt][hf] = m;
            }
        #pragma unroll
        for (int mt = 0; mt < 2; mt++)
            #pragma unroll
            for (int hf = 0; hf < 2; hf++)
                red[(wm2 + mt * 16 + (lane >> 2) + hf * 8) * 4 + wg] = rmax[mt][hf];
        __syncthreads();
        #pragma unroll
        for (int mt = 0; mt < 2; mt++)
            #pragma unroll
            for (int hf = 0; hf < 2; hf++) {
                const int r = wm2 + mt * 16 + (lane >> 2) + hf * 8;
                rmax[mt][hf] = fmaxf(fmaxf(red[r * 4], red[r * 4 + 1]),
                                     fmaxf(red[r * 4 + 2], red[r * 4 + 3]));
            }
        __syncthreads();

        // ---- exp + row sum ----
        float rsum[2][2];
        #pragma unroll
        for (int mt = 0; mt < 2; mt++)
            #pragma unroll
            for (int hf = 0; hf < 2; hf++) {
                float s = 0.0f;
                #pragma unroll
                for (int kc = 0; kc < 3; kc++)
                    #pragma unroll
                    for (int nt = 0; nt < 2; nt++)
                        #pragma unroll
                        for (int e = 0; e < 2; e++) {
                            float p = __expf(sacc[kc][mt][nt][hf * 2 + e] - rmax[mt][hf]);
                            sacc[kc][mt][nt][hf * 2 + e] = p;
                            s += p;
                        }
                s += __shfl_xor_sync(0xffffffffu, s, 1);
                s += __shfl_xor_sync(0xffffffffu, s, 2);
                rsum[mt][hf] = s;
            }
        #pragma unroll
        for (int mt = 0; mt < 2; mt++)
            #pragma unroll
            for (int hf = 0; hf < 2; hf++)
                red[(wm2 + mt * 16 + (lane >> 2) + hf * 8) * 4 + wg] = rsum[mt][hf];
        __syncthreads();
        #pragma unroll
        for (int mt = 0; mt < 2; mt++)
            #pragma unroll
            for (int hf = 0; hf < 2; hf++) {
                const int r = wm2 + mt * 16 + (lane >> 2) + hf * 8;
                rsum[mt][hf] = 1.0f / (red[r * 4] + red[r * 4 + 1] +
                                       red[r * 4 + 2] + red[r * 4 + 3]);
            }

        // ---- normalize, split to fp16 ph/pl ----
        #pragma unroll
        for (int kc = 0; kc < 3; kc++)
            #pragma unroll
            for (int mt = 0; mt < 2; mt++)
                #pragma unroll
                for (int nt = 0; nt < 2; nt++)
                    #pragma unroll
                    for (int hf = 0; hf < 2; hf++) {
                        const int row = wm2 + mt * 16 + (lane >> 2) + hf * 8;
                        const int col = kc * 64 + wn2 + nt * 8 + 2 * (lane & 3);
                        float p0 = sacc[kc][mt][nt][hf * 2]     * rsum[mt][hf];
                        float p1 = sacc[kc][mt][nt][hf * 2 + 1] * rsum[mt][hf];
                        __half h0 = __float2half(p0), h1 = __float2half(p1);
                        __half2 ph2(h0, h1);
                        __half2 pl2(__float2half(p0 - __half2float(h0)),
                                    __float2half(p1 - __half2float(h1)));
                        *(__half2*)(sm + PH_OFF + row * P_PITCH + col * 2) = ph2;
                        *(__half2*)(sm + PL_OFF + row * P_PITCH + col * 2) = pl2;
                    }

        // ---- PV: O = Ph*Vh + Ph*Vl + Pl*Vh ----
        const int wn2v = wg * 16;
        float oacc[2][2][4] = {};
        for (int kc = 0; kc < 3; kc++) {
            const int s0 = t0 - 64 + kc * 64;
            __syncthreads();
            #pragma unroll
            for (int t = 0; t < 2; t++) {
                const int seg = tid + t * 256;
                const int row = seg >> 3, sc = seg & 7;
                const int s = s0 + row;
                int4 vh = make_int4(0, 0, 0, 0), vl = make_int4(0, 0, 0, 0);
                if ((unsigned)s < (unsigned)S_) {
                    const size_t g = ((size_t)(b * S_ + s)) * HID_ + h * 64 + sc * 8;
                    vh = *(const int4*)(gVh + g);
                    vl = *(const int4*)(gVl + g);
                }
                const uint32_t off = SWZ128((uint32_t)(row * 128 + sc * 16));
                *(int4*)(sm + KVH_OFF + off) = vh;
                *(int4*)(sm + KVL_OFF + off) = vl;
            }
            __syncthreads();

            #pragma unroll
            for (int ks = 0; ks < 4; ks++) {
                uint32_t pa_h[2][4], pa_l[2][4], vh_[2][2], vl_[2][2];
                #pragma unroll
                for (int mt = 0; mt < 2; mt++) {
                    const uint32_t ao = (uint32_t)((wm2 + mt * 16 + arow) * P_PITCH
                                                   + kc * 128 + ks * 32 + ahalf);
                    ldmx4(pa_h[mt], smb + PH_OFF + ao);
                    ldmx4(pa_l[mt], smb + PL_OFF + ao);
                }
                const int krow = ks * 16 + arow;
                #pragma unroll
                for (int nt = 0; nt < 2; nt++) {
                    const uint32_t bo = SWZ128((uint32_t)(krow * 128
                                               + (wn2v + nt * 8) * 2));
                    ldmx2t(vh_[nt], smb + KVH_OFF + bo);
                    ldmx2t(vl_[nt], smb + KVL_OFF + bo);
                }
                #pragma unroll
                for (int mt = 0; mt < 2; mt++)
                    #pragma unroll
                    for (int nt = 0; nt < 2; nt++) {
                        mma_f16(oacc[mt][nt], pa_h[mt], vh_[nt]);
                        mma_f16(oacc[mt][nt], pa_h[mt], vl_[nt]);
                        mma_f16(oacc[mt][nt], pa_l[mt], vh_[nt]);
                    }
            }
        }

        // ---- epilogue: stage O (reuse Ph region), fp16 store to gAh ----
        __syncthreads();
        float* stage = (float*)(sm + PH_OFF);   // [64][68]
        #pragma unroll
        for (int mt = 0; mt < 2; mt++)
            #pragma unroll
            for (int nt = 0; nt < 2; nt++) {
                const int r = wm2 + mt * 16 + (lane >> 2);
                const int c = wn2v + nt * 8 + 2 * (lane & 3);
                *(float2*)&stage[r * 68 + c] =
                    make_float2(oacc[mt][nt][0], oacc[mt][nt][1]);
                *(float2*)&stage[(r + 8) * 68 + c] =
                    make_float2(oacc[mt][nt][2], oacc[mt][nt][3]);
            }
        __syncthreads();
        {
            const int row = tid >> 2, q4 = tid & 3;
            const size_t base = ((size_t)(b * S_ + t0 + row)) * HID_ + h * 64 + q4 * 16;
            const float* sp = &stage[row * 68 + q4 * 16];
            __half2 hbuf[8];
            #pragma unroll
            for (int e = 0; e < 8; e++)
                hbuf[e] = __floats2half2_rn(sp[2 * e], sp[2 * e + 1]);
            *(int4*)(gAh + base)     = *(int4*)&hbuf[0];
            *(int4*)(gAh + base + 8) = *(int4*)&hbuf[4];
        }
        __syncthreads();   // protect Qh/Ph overwrite on next tile
    }
}

// ---------------------------------------------------------------------------
extern "C" void kernel_launch(void* const* d_in, const int* in_sizes, int n_in,
                              void* d_out, int out_size) {
    const float* hidden = (const float*)d_in[0];
    const float* Wq     = (const float*)d_in[1];
    const float* Wo     = (const float*)d_in[2];
    float* out = (float*)d_out;
    (void)in_sizes; (void)n_in; (void)out_size;

    cudaFuncSetAttribute(gemm_mma<0>,
                         cudaFuncAttributeMaxDynamicSharedMemorySize, GT_SMEM);
    cudaFuncSetAttribute(gemm_mma<1>,
                         cudaFuncAttributeMaxDynamicSharedMemorySize, GT_SMEM);
    cudaFuncSetAttribute(attn_mma,
                         cudaFuncAttributeMaxDynamicSharedMemorySize, AT_SMEM);

    split_all<<<NB_H + 2 * NB_W, 256>>>(hidden, Wq, Wo);

    gemm_mma<0><<<GEMM_GRID, 256, GT_SMEM>>>(nullptr);

    attn_mma<<<GEMM_GRID, 256, AT_SMEM>>>();   // persistent, fp16

    gemm_mma<1><<<GEMM_GRID, 256, GT_SMEM>>>(out);
}

// round 17
// speedup vs baseline: 1.7000x; 1.1563x over previous
#include <cuda_runtime.h>
#include <cuda_bf16.h>
#include <cuda_fp16.h>
#include <math.h>
#include <stdint.h>

#define B_    2
#define S_    2048
#define HID_  768
#define NH_   12
#define HD_   64
#define M_    (B_ * S_)          // 4096 rows
#define WHALF 64                 // WINDOW/2

// ---------------- device scratch (no allocations allowed) ------------------
__device__ __align__(16) __half gAh[M_ * HID_];
__device__ __align__(16) __half gW1h[HID_ * HID_];
__device__ __align__(16) __half gW1l[HID_ * HID_];
__device__ __align__(16) __half gW2h[HID_ * HID_];
__device__ __align__(16) __half gW2l[HID_ * HID_];

// fp16 splits for attention (written by gemm<0> epilogue)
__device__ __align__(16) __half gKh[M_ * HID_];  // q_rot hi (= k = q)
__device__ __align__(16) __half gKl[M_ * HID_];  // q_rot lo
__device__ __align__(16) __half gVh[M_ * HID_];  // v hi
__device__ __align__(16) __half gVl[M_ * HID_];  // v lo

// persistent tile counters: [0]=gemm0, [1]=gemm1, [2]=attn (reset by split_all)
__device__ unsigned int gTileCtr[3];

// ---------------- PTX helpers (baseline ISA only) --------------------------
__device__ __forceinline__ uint32_t smem_u32(const void* p) {
    uint32_t a;
    asm("{ .reg .u64 t; cvta.to.shared.u64 t, %1; cvt.u32.u64 %0, t; }"
        : "=r"(a) : "l"(p));
    return a;
}
__device__ __forceinline__ void ldmx4(uint32_t r[4], uint32_t addr) {
    asm volatile("ldmatrix.sync.aligned.m8n8.x4.shared.b16 {%0,%1,%2,%3}, [%4];"
                 : "=r"(r[0]), "=r"(r[1]), "=r"(r[2]), "=r"(r[3]) : "r"(addr));
}
__device__ __forceinline__ void ldmx2(uint32_t r[2], uint32_t addr) {
    asm volatile("ldmatrix.sync.aligned.m8n8.x2.shared.b16 {%0,%1}, [%2];"
                 : "=r"(r[0]), "=r"(r[1]) : "r"(addr));
}
__device__ __forceinline__ void ldmx2t(uint32_t r[2], uint32_t addr) {
    asm volatile("ldmatrix.sync.aligned.m8n8.x2.trans.shared.b16 {%0,%1}, [%2];"
                 : "=r"(r[0]), "=r"(r[1]) : "r"(addr));
}
__device__ __forceinline__ void mma_f16(float c[4], const uint32_t a[4],
                                        const uint32_t b[2]) {
    asm volatile(
        "mma.sync.aligned.m16n8k16.row.col.f32.f16.f16.f32 "
        "{%0,%1,%2,%3}, {%4,%5,%6,%7}, {%8,%9}, {%0,%1,%2,%3};"
        : "+f"(c[0]), "+f"(c[1]), "+f"(c[2]), "+f"(c[3])
        : "r"(a[0]), "r"(a[1]), "r"(a[2]), "r"(a[3]), "r"(b[0]), "r"(b[1]));
}
__device__ __forceinline__ void cp16(uint32_t dst, const void* src) {
    asm volatile("cp.async.cg.shared.global [%0], [%1], 16;"
                 :: "r"(dst), "l"(src));
}
#define CP_COMMIT() asm volatile("cp.async.commit_group;" ::: "memory")
#define CP_WAIT1()  asm volatile("cp.async.wait_group 1;" ::: "memory")

#define SWZ64(off)  ((off) ^ (((off) >> 3) & 0x30))
#define SWZ128(off) ((off) ^ (((off) >> 3) & 0x70))

// ---------------------------------------------------------------------------
// merged split kernel: resets tile counters, then converts inputs to fp16.
// ---------------------------------------------------------------------------
#define NB_H ((M_ * HID_) / 1024)       // 3072
#define NB_W ((HID_ * HID_) / 1024)     // 576

__global__ __launch_bounds__(256)
void split_all(const float* __restrict__ hidden,
               const float* __restrict__ Wq,
               const float* __restrict__ Wo) {
    if (blockIdx.x == 0 && threadIdx.x == 0) {
        gTileCtr[0] = 0;
        gTileCtr[1] = 0;
        gTileCtr[2] = 0;
    }
    const int b = blockIdx.x;
    if (b < NB_H) {
        const int i = (b * 256 + threadIdx.x) * 4;
        float4 v = *(const float4*)(hidden + i);
        *(__half2*)(gAh + i)     = __floats2half2_rn(v.x, v.y);
        *(__half2*)(gAh + i + 2) = __floats2half2_rn(v.z, v.w);
        return;
    }
    const bool isW1 = (b < NB_H + NB_W);
    const float* __restrict__ src = isW1 ? Wq : Wo;
    __half* __restrict__ hi = isW1 ? gW1h : gW2h;
    __half* __restrict__ lo = isW1 ? gW1l : gW2l;
    const int bb = isW1 ? (b - NB_H) : (b - NB_H - NB_W);
    const int i = (bb * 256 + threadIdx.x) * 4;
    float4 v = *(const float4*)(src + i);
    __half h0 = __float2half(v.x), h1 = __float2half(v.y);
    __half h2 = __float2half(v.z), h3 = __float2half(v.w);
    *(__half2*)(hi + i)     = __half2(h0, h1);
    *(__half2*)(hi + i + 2) = __half2(h2, h3);
    __half l0 = __float2half(v.x - __half2float(h0));
    __half l1 = __float2half(v.y - __half2float(h1));
    __half l2 = __float2half(v.z - __half2float(h2));
    __half l3 = __float2half(v.w - __half2float(h3));
    *(__half2*)(lo + i)     = __half2(l0, l1);
    *(__half2*)(lo + i + 2) = __half2(l2, l3);
}

// ---------------------------------------------------------------------------
// PERSISTENT pipelined HMMA GEMM, fp16 2-term: C = Ah*Wh + Ah*Wl.
// Tile 64x64 (768 tiles, 5.2/SM -> fine-grained balance, small solo-tail).
// 256 threads = 8 warps 2(m)x4(n), warp tile 32x16; 2 CTA/SM (4 warps/SMSP).
// K chunks of 32, 3-stage cp.async pipeline.
// MODE 0: epilogue = RoPE + fp16 splits -> gKh/gKl, gVh/gVl.
// MODE 1: epilogue = fp32 store to out.
// ---------------------------------------------------------------------------
#define T_TILE_B  4096                      // 64 rows x 64 B (A, Wh, Wl each)
#define STAGE_B   (3 * T_TILE_B)            // 12288
#define STAGE_PITCH 68
#define GT_SMEM (1024 + 3 * STAGE_B + 16)   // 37920; epi overlay 17408 fits
#define IDX_OFF (1024 + 3 * STAGE_B)
#define NCHUNK (HID_ / 32)                  // 24
#define NTILES ((HID_ / 64) * (M_ / 64))    // 768
#define GEMM_GRID 296

template<int MODE>
__global__ __launch_bounds__(256, 2)
void gemm_mma(float* __restrict__ out) {
    extern __shared__ __align__(1024) char sm[];
    const uint32_t smb = smem_u32(sm);
    int* tslot = (int*)(sm + IDX_OFF);

    const int tid = threadIdx.x;
    const int wid = tid >> 5, lane = tid & 31;
    const int wm = (wid >> 2) * 32;       // 0/32
    const int wn = (wid & 3) * 16;        // 0/16/32/48

    const __half* __restrict__ Bh = (MODE == 0) ? gW1h : gW2h;
    const __half* __restrict__ Bl = (MODE == 0) ? gW1l : gW2l;

    const int lrow = tid >> 2;            // 0..63
    const int lseg = tid & 3;
    const uint32_t sa = SWZ64((uint32_t)(lrow * 64 + lseg * 16));
    const int arow = lane & 15;
    const int ahalf = (lane >> 4) << 4;
    const int brow = lane & 7;
    const int bhalf = ((lane >> 3) & 1) << 4;

    for (;;) {
        if (tid == 0)
            *tslot = (int)atomicAdd(&gTileCtr[MODE], 1u);
        __syncthreads();
        const int t = *tslot;
        if (t >= NTILES) break;
        const int n0 = (t % (HID_ / 64)) * 64;
        const int m0 = (t / (HID_ / 64)) * 64;

        const size_t gAr = (size_t)(m0 + lrow) * HID_ + lseg * 8;
        const size_t gWr = (size_t)(n0 + lrow) * HID_ + lseg * 8;

        #define LOAD_CHUNK(cc, st)                                            \
        {                                                                     \
            const int k0_ = (cc) * 32;                                        \
            const uint32_t s_ = smb + 1024 + (st) * STAGE_B;                  \
            cp16(s_ + sa,                gAh + gAr + k0_);                    \
            cp16(s_ + T_TILE_B + sa,     Bh + gWr + k0_);                     \
            cp16(s_ + 2 * T_TILE_B + sa, Bl + gWr + k0_);                     \
        }

        float acc[2][2][4] = {};

        LOAD_CHUNK(0, 0); CP_COMMIT();
        LOAD_CHUNK(1, 1); CP_COMMIT();

        int st = 0;
        for (int c = 0; c < NCHUNK; c++) {
            const uint32_t uA  = smb + 1024 + st * STAGE_B;
            const uint32_t uWh = uA + T_TILE_B;
            const uint32_t uWl = uA + 2 * T_TILE_B;

            CP_WAIT1();
            __syncthreads();

            if (c + 2 < NCHUNK) {
                const int st2 = (st + 2) % 3;
                LOAD_CHUNK(c + 2, st2);
            }
            CP_COMMIT();

            #pragma unroll
            for (int ks = 0; ks < 2; ks++) {
                const int kb = ks * 32;
                uint32_t ah[2][4], bh2[2][2], bl2[2][2];
                #pragma unroll
                for (int mt = 0; mt < 2; mt++) {
                    const int r = wm + mt * 16 + arow;
                    ldmx4(ah[mt], uA + SWZ64(r * 64 + kb + ahalf));
                }
                #pragma unroll
                for (int nt = 0; nt < 2; nt++) {
                    const int r = wn + nt * 8 + brow;
                    const uint32_t off = SWZ64(r * 64 + kb + bhalf);
                    ldmx2(bh2[nt], uWh + off);
                    ldmx2(bl2[nt], uWl + off);
                }
                #pragma unroll
                for (int mt = 0; mt < 2; mt++)
                    #pragma unroll
                    for (int nt = 0; nt < 2; nt++)
                        mma_f16(acc[mt][nt], ah[mt], bh2[nt]);
                #pragma unroll
                for (int mt = 0; mt < 2; mt++)
                    #pragma unroll
                    for (int nt = 0; nt < 2; nt++)
                        mma_f16(acc[mt][nt], ah[mt], bl2[nt]);
            }
            st = (st + 1) % 3;
        }
        #undef LOAD_CHUNK
        __syncthreads();

        // ---- epilogue: stage C in smem [64][68] fp32 ----
        float* stage = (float*)sm;
        #pragma unroll
        for (int mt = 0; mt < 2; mt++)
            #pragma unroll
            for (int nt = 0; nt < 2; nt++) {
                const int r = wm + mt * 16 + (lane >> 2);
                const int cc = wn + nt * 8 + 2 * (lane & 3);
                *(float2*)&stage[r * STAGE_PITCH + cc] =
                    make_float2(acc[mt][nt][0], acc[mt][nt][1]);
                *(float2*)&stage[(r + 8) * STAGE_PITCH + cc] =
                    make_float2(acc[mt][nt][2], acc[mt][nt][3]);
            }
        __syncthreads();

        const int row = tid >> 2;            // 0..63
        const int sub = tid & 3;
        const int m = m0 + row;
        if (MODE == 0) {
            // tile spans exactly one head (n0 multiple of 64).
            // thread owns lo cols d = sub*8..+7 paired with hi cols d+32.
            const float* srow = &stage[row * STAGE_PITCH + sub * 8];
            const float pos = (float)(m & (S_ - 1));
            float vb[16], rb[16];   // [0..7] lo, [8..15] hi
            #pragma unroll
            for (int j = 0; j < 8; j++) {
                const int d = sub * 8 + j;
                const float qlo = srow[j];
                const float qhi = srow[j + 32];
                const float inv = exp2f((float)d * -0.41524101186920654f);
                float sn, cs;
                sincosf(pos * inv, &sn, &cs);
                vb[j] = qlo;      vb[8 + j] = qhi;
                rb[j] = qlo * cs - qhi * sn;
                rb[8 + j] = qhi * cs + qlo * sn;
            }
            const size_t base = (size_t)m * HID_ + n0 + sub * 8;
            #pragma unroll
            for (int half = 0; half < 2; half++) {
                const size_t gb = base + half * 32;
                const float* vv = &vb[half * 8];
                const float* rr = &rb[half * 8];
                __half2 kh4[4], kl4[4], vh4[4], vl4[4];
                #pragma unroll
                for (int e = 0; e < 4; e++) {
                    float v0 = vv[2 * e], v1 = vv[2 * e + 1];
                    float r0 = rr[2 * e], r1 = rr[2 * e + 1];
                    __half vh0 = __float2half(v0), vh1 = __float2half(v1);
                    __half rh0 = __float2half(r0), rh1 = __float2half(r1);
                    vh4[e] = __half2(vh0, vh1);
                    vl4[e] = __half2(__float2half(v0 - __half2float(vh0)),
                                     __float2half(v1 - __half2float(vh1)));
                    kh4[e] = __half2(rh0, rh1);
                    kl4[e] = __half2(__float2half(r0 - __half2float(rh0)),
                                     __float2half(r1 - __half2float(rh1)));
                }
                *(int4*)(gKh + gb) = *(int4*)kh4;
                *(int4*)(gKl + gb) = *(int4*)kl4;
                *(int4*)(gVh + gb) = *(int4*)vh4;
                *(int4*)(gVl + gb) = *(int4*)vl4;
            }
        } else {
            const float* srow = &stage[row * STAGE_PITCH + sub * 16];
            float* op = &out[(size_t)m * HID_ + n0 + sub * 16];
            #pragma unroll
            for (int qq = 0; qq < 4; qq++) {
                float4 f = make_float4(srow[qq * 4], srow[qq * 4 + 1],
                                       srow[qq * 4 + 2], srow[qq * 4 + 3]);
                *(float4*)(op + qq * 4) = f;
            }
        }
        __syncthreads();
    }
}

// ---------------------------------------------------------------------------
// PERSISTENT HMMA sliding-window attention, fp16.
// Scores 2-term: S = Qh*Kh + Qh*Kl. PV 2-term: O = Ph*Vh + Ph*Vl.
// smem: Qh 8KB, KVh 8KB, KVl 8KB, Ph 25.6KB, red 1KB, idx 16B
// ---------------------------------------------------------------------------
#define QH_OFF   0
#define KVH_OFF  8192
#define KVL_OFF  16384
#define PH_OFF   24576
#define RED_OFF  50176
#define AIDX_OFF 51200
#define AT_SMEM  51232
#define P_PITCH  400
#define NT_AT    ((S_ / 64) * B_ * NH_)   // 768

__global__ __launch_bounds__(256, 2)
void attn_mma() {
    extern __shared__ __align__(1024) char sm[];
    const uint32_t smb = smem_u32(sm);
    int* tslot = (int*)(sm + AIDX_OFF);
    float* red = (float*)(sm + RED_OFF);

    const int tid = threadIdx.x;
    const int wid = tid >> 5, lane = tid & 31;
    const int wm2 = (wid >> 2) * 32;
    const int wg  = wid & 3;
    const int wn2 = wg * 16;

    const int arow = lane & 15;
    const int ahalf = (lane >> 4) << 4;
    const int brow = lane & 7;
    const int bhalf = ((lane >> 3) & 1) << 4;

    for (;;) {
        if (tid == 0)
            *tslot = (int)atomicAdd(&gTileCtr[2], 1u);
        __syncthreads();
        const int tt = *tslot;
        if (tt >= NT_AT) break;
        const int t0 = (tt & 31) * 64;
        const int bh = tt >> 5;
        const int b = bh / NH_, h = bh % NH_;

        // ---- load Q (hi only) ----
        #pragma unroll
        for (int t = 0; t < 2; t++) {
            const int seg = tid + t * 256;
            const int row = seg >> 3, sc = seg & 7;
            const size_t g = ((size_t)(b * S_ + t0 + row)) * HID_ + h * 64 + sc * 8;
            const uint32_t off = SWZ128((uint32_t)(row * 128 + sc * 16));
            *(int4*)(sm + QH_OFF + off) = *(const int4*)(gKh + g);
        }

        // ---- score phase: 3 key chunks, 2-term fp16 ----
        float sacc[3][2][2][4] = {};
        for (int kc = 0; kc < 3; kc++) {
            const int s0 = t0 - 64 + kc * 64;
            __syncthreads();
            #pragma unroll
            for (int t = 0; t < 2; t++) {
                const int seg = tid + t * 256;
                const int row = seg >> 3, sc = seg & 7;
                const int s = s0 + row;
                int4 vh = make_int4(0, 0, 0, 0), vl = make_int4(0, 0, 0, 0);
                if ((unsigned)s < (unsigned)S_) {
                    const size_t g = ((size_t)(b * S_ + s)) * HID_ + h * 64 + sc * 8;
                    vh = *(const int4*)(gKh + g);
                    vl = *(const int4*)(gKl + g);
                }
                const uint32_t off = SWZ128((uint32_t)(row * 128 + sc * 16));
                *(int4*)(sm + KVH_OFF + off) = vh;
                *(int4*)(sm + KVL_OFF + off) = vl;
            }
            __syncthreads();

            #pragma unroll
            for (int ks = 0; ks < 4; ks++) {
                const int kb = ks * 32;
                uint32_t qh_[2][4], kh_[2][2], kl_[2][2];
                #pragma unroll
                for (int mt = 0; mt < 2; mt++) {
                    const uint32_t ao = SWZ128((wm2 + mt * 16 + arow) * 128 + kb + ahalf);
                    ldmx4(qh_[mt], smb + QH_OFF + ao);
                }
                #pragma unroll
                for (int nt = 0; nt < 2; nt++) {
                    const uint32_t bo = SWZ128((wn2 + nt * 8 + brow) * 128 + kb + bhalf);
                    ldmx2(kh_[nt], smb + KVH_OFF + bo);
                    ldmx2(kl_[nt], smb + KVL_OFF + bo);
                }
                #pragma unroll
                for (int mt = 0; mt < 2; mt++)
                    #pragma unroll
                    for (int nt = 0; nt < 2; nt++) {
                        mma_f16(sacc[kc][mt][nt], qh_[mt], kh_[nt]);
                        mma_f16(sacc[kc][mt][nt], qh_[mt], kl_[nt]);
                    }
            }
        }

        // ---- mask + scale ----
        #pragma unroll
        for (int kc = 0; kc < 3; kc++)
            #pragma unroll
            for (int mt = 0; mt < 2; mt++)
                #pragma unroll
                for (int nt = 0; nt < 2; nt++)
                    #pragma unroll
                    for (int j = 0; j < 4; j++) {
                        const int row = wm2 + mt * 16 + (lane >> 2) + (j >> 1) * 8;
                        const int col = kc * 64 + wn2 + nt * 8 + 2 * (lane & 3) + (j & 1);
                        const int t = t0 + row;
                        const int s = t0 - 64 + col;
                        int dist = t - s; if (dist < 0) dist = -dist;
                        const bool valid = ((unsigned)s < (unsigned)S_) && (dist <= WHALF);
                        sacc[kc][mt][nt][j] = valid ? sacc[kc][mt][nt][j] * 0.125f : -1e30f;
                    }

        // ---- softmax: row max ----
        float rmax[2][2];
        #pragma unroll
        for (int mt = 0; mt < 2; mt++)
            #pragma unroll
            for (int hf = 0; hf < 2; hf++) {
                float m = -1e30f;
                #pragma unroll
                for (int kc = 0; kc < 3; kc++)
                    #pragma unroll
                    for (int nt = 0; nt < 2; nt++) {
                        m = fmaxf(m, sacc[kc][mt][nt][hf * 2]);
                        m = fmaxf(m, sacc[kc][mt][nt][hf * 2 + 1]);
                    }
                m = fmaxf(m, __shfl_xor_sync(0xffffffffu, m, 1));
                m = fmaxf(m, __shfl_xor_sync(0xffffffffu, m, 2));
                rmax[mt][hf] = m;
            }
        #pragma unroll
        for (int mt = 0; mt < 2; mt++)
            #pragma unroll
            for (int hf = 0; hf < 2; hf++)
                red[(wm2 + mt * 16 + (lane >> 2) + hf * 8) * 4 + wg] = rmax[mt][hf];
        __syncthreads();
        #pragma unroll
        for (int mt = 0; mt < 2; mt++)
            #pragma unroll
            for (int hf = 0; hf < 2; hf++) {
                const int r = wm2 + mt * 16 + (lane >> 2) + hf * 8;
                rmax[mt][hf] = fmaxf(fmaxf(red[r * 4], red[r * 4 + 1]),
                                     fmaxf(red[r * 4 + 2], red[r * 4 + 3]));
            }
        __syncthreads();

        // ---- exp + row sum ----
        float rsum[2][2];
        #pragma unroll
        for (int mt = 0; mt < 2; mt++)
            #pragma unroll
            for (int hf = 0; hf < 2; hf++) {
                float s = 0.0f;
                #pragma unroll
                for (int kc = 0; kc < 3; kc++)
                    #pragma unroll
                    for (int nt = 0; nt < 2; nt++)
                        #pragma unroll
                        for (int e = 0; e < 2; e++) {
                            float p = __expf(sacc[kc][mt][nt][hf * 2 + e] - rmax[mt][hf]);
                            sacc[kc][mt][nt][hf * 2 + e] = p;
                            s += p;
                        }
                s += __shfl_xor_sync(0xffffffffu, s, 1);
                s += __shfl_xor_sync(0xffffffffu, s, 2);
                rsum[mt][hf] = s;
            }
        #pragma unroll
        for (int mt = 0; mt < 2; mt++)
            #pragma unroll
            for (int hf = 0; hf < 2; hf++)
                red[(wm2 + mt * 16 + (lane >> 2) + hf * 8) * 4 + wg] = rsum[mt][hf];
        __syncthreads();
        #pragma unroll
        for (int mt = 0; mt < 2; mt++)
            #pragma unroll
            for (int hf = 0; hf < 2; hf++) {
                const int r = wm2 + mt * 16 + (lane >> 2) + hf * 8;
                rsum[mt][hf] = 1.0f / (red[r * 4] + red[r * 4 + 1] +
                                       red[r * 4 + 2] + red[r * 4 + 3]);
            }

        // ---- normalize, store fp16 Ph ----
        #pragma unroll
        for (int kc = 0; kc < 3; kc++)
            #pragma unroll
            for (int mt = 0; mt < 2; mt++)
                #pragma unroll
                for (int nt = 0; nt < 2; nt++)
                    #pragma unroll
                    for (int hf = 0; hf < 2; hf++) {
                        const int row = wm2 + mt * 16 + (lane >> 2) + hf * 8;
                        const int col = kc * 64 + wn2 + nt * 8 + 2 * (lane & 3);
                        float p0 = sacc[kc][mt][nt][hf * 2]     * rsum[mt][hf];
                        float p1 = sacc[kc][mt][nt][hf * 2 + 1] * rsum[mt][hf];
                        *(__half2*)(sm + PH_OFF + row * P_PITCH + col * 2) =
                            __floats2half2_rn(p0, p1);
                    }

        // ---- PV: O = Ph*Vh + Ph*Vl ----
        const int wn2v = wg * 16;
        float oacc[2][2][4] = {};
        for (int kc = 0; kc < 3; kc++) {
            const int s0 = t0 - 64 + kc * 64;
            __syncthreads();
            #pragma unroll
            for (int t = 0; t < 2; t++) {
                const int seg = tid + t * 256;
                const int row = seg >> 3, sc = seg & 7;
                const int s = s0 + row;
                int4 vh = make_int4(0, 0, 0, 0), vl = make_int4(0, 0, 0, 0);
                if ((unsigned)s < (unsigned)S_) {
                    const size_t g = ((size_t)(b * S_ + s)) * HID_ + h * 64 + sc * 8;
                    vh = *(const int4*)(gVh + g);
                    vl = *(const int4*)(gVl + g);
                }
                const uint32_t off = SWZ128((uint32_t)(row * 128 + sc * 16));
                *(int4*)(sm + KVH_OFF + off) = vh;
                *(int4*)(sm + KVL_OFF + off) = vl;
            }
            __syncthreads();

            #pragma unroll
            for (int ks = 0; ks < 4; ks++) {
                uint32_t pa_h[2][4], vh_[2][2], vl_[2][2];
                #pragma unroll
                for (int mt = 0; mt < 2; mt++) {
                    const uint32_t ao = (uint32_t)((wm2 + mt * 16 + arow) * P_PITCH
                                                   + kc * 128 + ks * 32 + ahalf);
                    ldmx4(pa_h[mt], smb + PH_OFF + ao);
                }
                const int krow = ks * 16 + arow;
                #pragma unroll
                for (int nt = 0; nt < 2; nt++) {
                    const uint32_t bo = SWZ128((uint32_t)(krow * 128
                                               + (wn2v + nt * 8) * 2));
                    ldmx2t(vh_[nt], smb + KVH_OFF + bo);
                    ldmx2t(vl_[nt], smb + KVL_OFF + bo);
                }
                #pragma unroll
                for (int mt = 0; mt < 2; mt++)
                    #pragma unroll
                    for (int nt = 0; nt < 2; nt++) {
                        mma_f16(oacc[mt][nt], pa_h[mt], vh_[nt]);
                        mma_f16(oacc[mt][nt], pa_h[mt], vl_[nt]);
                    }
            }
        }

        // ---- epilogue: stage O (reuse Ph region), fp16 store to gAh ----
        __syncthreads();
        float* stage = (float*)(sm + PH_OFF);   // [64][68]
        #pragma unroll
        for (int mt = 0; mt < 2; mt++)
            #pragma unroll
            for (int nt = 0; nt < 2; nt++) {
                const int r = wm2 + mt * 16 + (lane >> 2);
                const int c = wn2v + nt * 8 + 2 * (lane & 3);
                *(float2*)&stage[r * 68 + c] =
                    make_float2(oacc[mt][nt][0], oacc[mt][nt][1]);
                *(float2*)&stage[(r + 8) * 68 + c] =
                    make_float2(oacc[mt][nt][2], oacc[mt][nt][3]);
            }
        __syncthreads();
        {
            const int row = tid >> 2, q4 = tid & 3;
            const size_t base = ((size_t)(b * S_ + t0 + row)) * HID_ + h * 64 + q4 * 16;
            const float* sp = &stage[row * 68 + q4 * 16];
            __half2 hbuf[8];
            #pragma unroll
            for (int e = 0; e < 8; e++)
                hbuf[e] = __floats2half2_rn(sp[2 * e], sp[2 * e + 1]);
            *(int4*)(gAh + base)     = *(int4*)&hbuf[0];
            *(int4*)(gAh + base + 8) = *(int4*)&hbuf[4];
        }
        __syncthreads();
    }
}

// ---------------------------------------------------------------------------
extern "C" void kernel_launch(void* const* d_in, const int* in_sizes, int n_in,
                              void* d_out, int out_size) {
    const float* hidden = (const float*)d_in[0];
    const float* Wq     = (const float*)d_in[1];
    const float* Wo     = (const float*)d_in[2];
    float* out = (float*)d_out;
    (void)in_sizes; (void)n_in; (void)out_size;

    cudaFuncSetAttribute(gemm_mma<0>,
                         cudaFuncAttributeMaxDynamicSharedMemorySize, GT_SMEM);
    cudaFuncSetAttribute(gemm_mma<1>,
                         cudaFuncAttributeMaxDynamicSharedMemorySize, GT_SMEM);
    cudaFuncSetAttribute(attn_mma,
                         cudaFuncAttributeMaxDynamicSharedMemorySize, AT_SMEM);

    split_all<<<NB_H + 2 * NB_W, 256>>>(hidden, Wq, Wo);

    gemm_mma<0><<<GEMM_GRID, 256, GT_SMEM>>>(nullptr);

    attn_mma<<<GEMM_GRID, 256, AT_SMEM>>>();   // persistent, fp16

    gemm_mma<1><<<GEMM_GRID, 256, GT_SMEM>>>(out);
}